// round 11
// baseline (speedup 1.0000x reference)
#include <cuda_runtime.h>

#define D   256
#define PP  512
#define HH  8
#define DA  64
#define TMAX 65536
typedef unsigned long long u64;

// ---------------- device scratch ----------------
__device__ float g_kQ  [HH * 16 * PP * 4];        // [h][d4][p]{d0..d3}
__device__ float g_vP4 [HH * 128 * DA * 4];       // [h][p4][d]{p0..p3}
__device__ float g_xn  [(size_t)TMAX * D];
__device__ float g_att [(size_t)TMAX * HH * DA];
__device__ float g_wqP4  [64 * 512 * 4];          // [k4][j]{k0..k3}
__device__ float g_woutP4[128 * 256 * 4];         // [k4][c]{k0..k3}
__device__ float g_cwT  [3 * D * D];              // [tap][i][c]
__device__ float g_wkvT [D * 1024];               // [k][j]

// ---------------- f32x2 helpers ----------------
__device__ __forceinline__ u64 pack2(float x, float y) {
    u64 r; asm("mov.b64 %0,{%1,%2};" : "=l"(r) : "f"(x), "f"(y)); return r;
}
__device__ __forceinline__ u64 dup2(float x) { return pack2(x, x); }
__device__ __forceinline__ void fma2(u64& d, u64 a, u64 b) {
    asm("fma.rn.f32x2 %0,%1,%2,%0;" : "+l"(d) : "l"(a), "l"(b));
}
__device__ __forceinline__ float2 u2f(u64 v) {
    float2 f; asm("mov.b64 {%0,%1},%2;" : "=f"(f.x), "=f"(f.y) : "l"(v)); return f;
}

// ---------------- launch 1: weight reshapes ----------------
// grid 1216 x 256
__global__ void prep_kernel(const float* __restrict__ wq,
                            const float* __restrict__ wkv,
                            const float* __restrict__ wout,
                            const float* __restrict__ cw) {
    int bid = blockIdx.x, t = threadIdx.x;
    if (bid < 128) {                       // woutP4
        int k4 = bid;
        #pragma unroll
        for (int kk = 0; kk < 4; kk++)
            g_woutP4[(k4 * 256 + t) * 4 + kk] = wout[t * 512 + 4 * k4 + kk];
    } else if (bid < 192) {                // wqP4
        int k4 = bid - 128;
        #pragma unroll
        for (int u = 0; u < 2; u++) {
            int j = t + u * 256;
            #pragma unroll
            for (int kk = 0; kk < 4; kk++)
                g_wqP4[(k4 * 512 + j) * 4 + kk] = wq[j * 256 + 4 * k4 + kk];
        }
    } else if (bid < 448) {                // wkvT
        int k = bid - 192;
        #pragma unroll
        for (int u = 0; u < 4; u++)
            g_wkvT[k * 1024 + t + u * 256] = wkv[(size_t)(t + u * 256) * 256 + k];
    } else {                               // cwT
        int idx = bid - 448;
        int tap = idx >> 8, i = idx & 255;
        g_cwT[tap * 65536 + i * 256 + t] = cw[t * 768 + i * 3 + tap];
    }
}

// ---------------- launch 2: pattern double-LN + kv projection ----------------
__device__ __forceinline__ float block_reduce_sum256(float v, float* scratch) {
    #pragma unroll
    for (int o = 16; o; o >>= 1) v += __shfl_xor_sync(0xffffffffu, v, o);
    int w = threadIdx.x >> 5;
    if ((threadIdx.x & 31) == 0) scratch[w] = v;
    __syncthreads();
    if (threadIdx.x < 32) {
        float s = (threadIdx.x < 8) ? scratch[threadIdx.x] : 0.f;
        #pragma unroll
        for (int o = 4; o; o >>= 1) s += __shfl_xor_sync(0xffffffffu, s, o);
        if (threadIdx.x == 0) scratch[0] = s;
    }
    __syncthreads();
    float r = scratch[0];
    __syncthreads();
    return r;
}

__global__ void kv_kernel(const float* __restrict__ pattern) {
    __shared__ float scr[8];
    __shared__ float pr[D];
    int p = blockIdx.x, t = threadIdx.x;
    float v = pattern[p * D + t];
    #pragma unroll
    for (int rep = 0; rep < 2; rep++) {
        float s  = block_reduce_sum256(v, scr);
        float s2 = block_reduce_sum256(v * v, scr);
        float mu  = s * (1.f / D);
        v = (v - mu) * rsqrtf(s2 * (1.f / D) - mu * mu + 1e-5f);
    }
    pr[t] = v;
    __syncthreads();
    float acc[4] = {0.f, 0.f, 0.f, 0.f};
    for (int i = 0; i < D; i++) {
        float xv = pr[i];
        const float* wr = g_wkvT + i * 1024 + t;
        #pragma unroll
        for (int u = 0; u < 4; u++) acc[u] = fmaf(xv, wr[u * 256], acc[u]);
    }
    #pragma unroll
    for (int u = 0; u < 4; u++) {
        int j = t + u * 256;
        int h = j >> 7, r = j & 127;
        if (r < DA) {   // K element (p, h, d=r)
            g_kQ[(((h * 16) + (r >> 2)) * 512 + p) * 4 + (r & 3)] = acc[u];
        } else {        // V element (p, h, d=r-64)
            int dc = r - DA;
            g_vP4[((h * 128 + (p >> 2)) * 64 + dc) * 4 + (p & 3)] = acc[u];
        }
    }
}

// ---------------- launch 3: conv + residual + leaky + LN ----------------
__global__ __launch_bounds__(256, 2) void convln_kernel(const float* __restrict__ x,
                                                        const float* __restrict__ conv_b,
                                                        int L) {
    extern __shared__ float sm[];
    float* xs = sm;              // [34][256]
    float* ys = sm + 34 * D;     // [32][256]
    float* st = ys + 32 * D;     // 64
    int tid = threadIdx.x;
    int c2 = tid & 127, th = tid >> 7;
    int t0 = blockIdx.x * 32;
    int pos0 = t0 % L;
    for (int r = 0; r < 34; r++) {
        float v = 0.f;
        if (pos0 + r >= 2) v = x[(size_t)(t0 + r - 2) * D + tid];
        xs[r * D + tid] = v;
    }
    __syncthreads();

    int m0 = th * 16;
    u64 acc[16];
    {
        float2 b = *(const float2*)&conv_b[2 * c2];
        u64 bp = pack2(b.x, b.y);
        #pragma unroll
        for (int j = 0; j < 16; j++) acc[j] = bp;
    }
    const float* cw0 = g_cwT + 2 * c2;
    for (int i = 0; i < D; i++) {
        u64 w0 = *(const u64*)(cw0 +           i * 256);
        u64 w1 = *(const u64*)(cw0 +  65536 + i * 256);
        u64 w2 = *(const u64*)(cw0 + 131072 + i * 256);
        u64 xa = dup2(xs[(m0)     * D + i]);
        u64 xb = dup2(xs[(m0 + 1) * D + i]);
        #pragma unroll
        for (int j = 0; j < 16; j++) {
            u64 xc = dup2(xs[(m0 + j + 2) * D + i]);
            fma2(acc[j], w0, xa);
            fma2(acc[j], w1, xb);
            fma2(acc[j], w2, xc);
            xa = xb; xb = xc;
        }
    }
    #pragma unroll
    for (int j = 0; j < 16; j++) {
        int m = m0 + j;
        float2 f = u2f(acc[j]);
        float2 res = *(const float2*)&xs[(m + 2) * D + 2 * c2];
        float v0 = f.x + res.x, v1 = f.y + res.y;
        v0 = v0 > 0.f ? v0 : 0.01f * v0;
        v1 = v1 > 0.f ? v1 : 0.01f * v1;
        *(float2*)&ys[m * D + 2 * c2] = make_float2(v0, v1);
    }
    __syncthreads();

    int lane = tid & 31, warp = tid >> 5;
    for (int jj = 0; jj < 4; jj++) {
        int m = warp + 8 * jj;
        float s = 0.f, s2 = 0.f;
        #pragma unroll
        for (int q = 0; q < 8; q++) {
            float v = ys[m * D + q * 32 + lane];
            s += v; s2 += v * v;
        }
        #pragma unroll
        for (int o = 16; o; o >>= 1) {
            s  += __shfl_xor_sync(0xffffffffu, s, o);
            s2 += __shfl_xor_sync(0xffffffffu, s2, o);
        }
        if (lane == 0) {
            float mu = s * (1.f / D);
            st[m]      = mu;
            st[32 + m] = rsqrtf(s2 * (1.f / D) - mu * mu + 1e-5f);
        }
    }
    __syncthreads();
    #pragma unroll
    for (int m = 0; m < 32; m++)
        g_xn[(size_t)(t0 + m) * D + tid] = (ys[m * D + tid] - st[m]) * st[32 + m];
}

// ---------------- launch 4 (PROFILED): fused qproj + attention ----------------
// grid (T/32, 8); 256 threads
// smem: qs [32][68] | rb [32] | part [2][32][64] | union{ xs [32][260], probsT [32][516] }
__global__ __launch_bounds__(256, 2) void attn_kernel() {
    extern __shared__ float sm[];
    float* qs   = sm;               // 2176
    float* rb   = sm + 2176;        // 32
    float* part = sm + 2208;        // 4096
    float* buf  = sm + 6304;        // 16512
    int tid = threadIdx.x, lane = tid & 31, w = tid >> 5;
    int t0 = blockIdx.x * 32, h = blockIdx.y;

    // ---- stage xs token-major [32][260] ----
    float* xs = buf;
    {
        int tok = tid >> 3, q0 = tid & 7;
        const float4* src = (const float4*)&g_xn[(size_t)(t0 + tok) * D];
        float4* dst = (float4*)&xs[tok * 260];
        #pragma unroll
        for (int i = 0; i < 8; i++) dst[q0 + 8 * i] = src[q0 + 8 * i];
    }
    __syncthreads();

    // ---- phase 1: q-proj. warp w -> toks 4w..4w+3; cols lane, lane+32 ----
    {
        u64 acc[4][2];
        #pragma unroll
        for (int tt = 0; tt < 4; tt++) { acc[tt][0] = 0; acc[tt][1] = 0; }
        const float* wb = g_wqP4 + (h * 64 + lane) * 4;
        #pragma unroll 2
        for (int k4 = 0; k4 < 64; k4++) {
            const float* wr = wb + k4 * 2048;
            ulonglong2 B0 = *(const ulonglong2*)(wr);
            ulonglong2 B1 = *(const ulonglong2*)(wr + 128);
            #pragma unroll
            for (int tt = 0; tt < 4; tt++) {
                ulonglong2 A = *(const ulonglong2*)&xs[(4 * w + tt) * 260 + 4 * k4];
                fma2(acc[tt][0], A.x, B0.x); fma2(acc[tt][0], A.y, B0.y);
                fma2(acc[tt][1], A.x, B1.x); fma2(acc[tt][1], A.y, B1.y);
            }
        }
        #pragma unroll
        for (int tt = 0; tt < 4; tt++) {
            float2 f0 = u2f(acc[tt][0]), f1 = u2f(acc[tt][1]);
            qs[(4 * w + tt) * 68 + lane]      = f0.x + f0.y;
            qs[(4 * w + tt) * 68 + lane + 32] = f1.x + f1.y;
        }
    }
    __syncthreads();

    // ---- phase 2: scores + exp ----
    // warp w: toks 8(w&3)..+7; slice ps=(w>>2); 2 passes over 128-pat quarters:
    //   pats = ps*256 + pass*128 + lane + 32j, j=0..3
    float* probsT = buf;            // xs dead
    {
        int tg = w & 3, ps = w >> 2;
        int tokb = tg * 8;
        const float* kb = g_kQ + ((size_t)(h * 16) * 512 + ps * 256 + lane) * 4;
        #pragma unroll
        for (int pass = 0; pass < 2; pass++) {
            u64 acc[8][4];
            #pragma unroll
            for (int tt = 0; tt < 8; tt++)
                #pragma unroll
                for (int j = 0; j < 4; j++) acc[tt][j] = 0;
            for (int d4 = 0; d4 < 16; d4++) {
                const float* kr = kb + d4 * 2048 + pass * 512;
                ulonglong2 B[4];
                #pragma unroll
                for (int j = 0; j < 4; j++) B[j] = *(const ulonglong2*)(kr + j * 128);
                #pragma unroll
                for (int tt = 0; tt < 8; tt++) {
                    ulonglong2 A = *(const ulonglong2*)&qs[(tokb + tt) * 68 + 4 * d4];
                    #pragma unroll
                    for (int j = 0; j < 4; j++) {
                        fma2(acc[tt][j], A.x, B[j].x);
                        fma2(acc[tt][j], A.y, B[j].y);
                    }
                }
            }
            #pragma unroll
            for (int tt = 0; tt < 8; tt++)
                #pragma unroll
                for (int j = 0; j < 4; j++) {
                    float2 f = u2f(acc[tt][j]);
                    probsT[(tokb + tt) * 516 + ps * 256 + pass * 128 + lane + 32 * j] =
                        __expf(0.125f * (f.x + f.y));
                }
        }
    }
    __syncthreads();

    // ---- phase 3: per-token prob sums (warp w -> toks 4w..4w+3) ----
    #pragma unroll
    for (int tt = 0; tt < 4; tt++) {
        int tok = 4 * w + tt;
        float s = 0.f;
        #pragma unroll
        for (int i = 0; i < 16; i++) s += probsT[tok * 516 + lane + 32 * i];
        #pragma unroll
        for (int o = 16; o; o >>= 1) s += __shfl_xor_sync(0xffffffffu, s, o);
        if (lane == 0) rb[tok] = 1.f / s;
    }
    __syncthreads();

    // ---- phase 4: PV. warp w: toks 8(w&3)..+7; p-half (w>>2); d = lane, lane+32 ----
    {
        int tg = w & 3, ph = w >> 2;
        int tokb = tg * 8;
        u64 acc[8][2];
        #pragma unroll
        for (int tt = 0; tt < 8; tt++) { acc[tt][0] = 0; acc[tt][1] = 0; }
        const float* vb = g_vP4 + ((size_t)(h * 128 + ph * 64) * 64 + lane) * 4;
        #pragma unroll 2
        for (int p4 = 0; p4 < 64; p4++) {
            const float* vr = vb + p4 * 256;
            ulonglong2 B0 = *(const ulonglong2*)(vr);          // d = lane
            ulonglong2 B1 = *(const ulonglong2*)(vr + 128);    // d = lane+32
            #pragma unroll
            for (int tt = 0; tt < 8; tt++) {
                ulonglong2 A = *(const ulonglong2*)&probsT[(tokb + tt) * 516 + ph * 256 + 4 * p4];
                fma2(acc[tt][0], A.x, B0.x); fma2(acc[tt][0], A.y, B0.y);
                fma2(acc[tt][1], A.x, B1.x); fma2(acc[tt][1], A.y, B1.y);
            }
        }
        #pragma unroll
        for (int tt = 0; tt < 8; tt++) {
            float2 f0 = u2f(acc[tt][0]), f1 = u2f(acc[tt][1]);
            part[(ph * 32 + tokb + tt) * 64 + lane]      = f0.x + f0.y;
            part[(ph * 32 + tokb + tt) * 64 + lane + 32] = f1.x + f1.y;
        }
    }
    __syncthreads();

    // ---- phase 5: combine p-halves, scale, store ----
    #pragma unroll
    for (int k = 0; k < 8; k++) {
        int idx = k * 256 + tid;
        int tok = idx >> 6, d = idx & 63;
        float v = (part[(tok) * 64 + d] + part[(32 + tok) * 64 + d]) * rb[tok];
        g_att[(size_t)(t0 + tok) * 512 + h * 64 + d] = v;
    }
}

// ---------------- launch 5: out projection + final LN ----------------
__global__ __launch_bounds__(256, 2) void outln_kernel(const float* __restrict__ bout,
                                                       float* __restrict__ out) {
    extern __shared__ float sm[];
    float* as_ = sm;             // [32][516]
    int tid = threadIdx.x, lane = tid & 31, w = tid >> 5;
    int t0 = blockIdx.x * 32;

    {
        int tok = tid >> 3, q0 = tid & 7;
        const float4* src = (const float4*)&g_att[(size_t)(t0 + tok) * 512];
        float4* dst = (float4*)&as_[tok * 516];
        #pragma unroll
        for (int i = 0; i < 16; i++) dst[q0 + 8 * i] = src[q0 + 8 * i];
    }
    __syncthreads();

    u64 acc[4][8];
    #pragma unroll
    for (int tt = 0; tt < 4; tt++)
        #pragma unroll
        for (int j = 0; j < 8; j++) acc[tt][j] = 0;
    const float* wb = g_woutP4 + lane * 4;
    for (int k4 = 0; k4 < 128; k4++) {
        const float* wr = wb + k4 * 1024;
        ulonglong2 B[8];
        #pragma unroll
        for (int j = 0; j < 8; j++) B[j] = *(const ulonglong2*)(wr + j * 128);
        #pragma unroll
        for (int tt = 0; tt < 4; tt++) {
            ulonglong2 A = *(const ulonglong2*)&as_[(4 * w + tt) * 516 + 4 * k4];
            #pragma unroll
            for (int j = 0; j < 8; j++) {
                fma2(acc[tt][j], A.x, B[j].x);
                fma2(acc[tt][j], A.y, B[j].y);
            }
        }
    }
    #pragma unroll
    for (int tt = 0; tt < 4; tt++) {
        int tok = 4 * w + tt;
        float vals[8];
        float s = 0.f, s2 = 0.f;
        #pragma unroll
        for (int j = 0; j < 8; j++) {
            float2 f = u2f(acc[tt][j]);
            float v = f.x + f.y + __ldg(&bout[lane + 32 * j]);
            vals[j] = v;
            s += v; s2 += v * v;
        }
        #pragma unroll
        for (int o = 16; o; o >>= 1) {
            s  += __shfl_xor_sync(0xffffffffu, s, o);
            s2 += __shfl_xor_sync(0xffffffffu, s2, o);
        }
        float mu = s * (1.f / D);
        float rstd = rsqrtf(s2 * (1.f / D) - mu * mu + 1e-5f);
        #pragma unroll
        for (int j = 0; j < 8; j++)
            out[(size_t)(t0 + tok) * D + lane + 32 * j] = (vals[j] - mu) * rstd;
    }
}

// ---------------- launch ----------------
extern "C" void kernel_launch(void* const* d_in, const int* in_sizes, int n_in,
                              void* d_out, int out_size) {
    const float* x       = (const float*)d_in[0];
    const float* conv_w  = (const float*)d_in[1];
    const float* conv_b  = (const float*)d_in[2];
    const float* pattern = (const float*)d_in[3];
    const float* wq      = (const float*)d_in[4];
    const float* wkv     = (const float*)d_in[5];
    const float* wout    = (const float*)d_in[6];
    const float* bout    = (const float*)d_in[7];

    int T = in_sizes[0] / D;
    int B = in_sizes[8] - 1;
    int L = T / B;

    int convln_smem = (34 * D + 32 * D + 64) * 4;          // 67840
    int attn_smem   = (2176 + 32 + 4096 + 16512) * 4;      // 91264
    int outln_smem  = (32 * 516) * 4;                      // 66048
    cudaFuncSetAttribute(convln_kernel, cudaFuncAttributeMaxDynamicSharedMemorySize, convln_smem);
    cudaFuncSetAttribute(attn_kernel,   cudaFuncAttributeMaxDynamicSharedMemorySize, attn_smem);
    cudaFuncSetAttribute(outln_kernel,  cudaFuncAttributeMaxDynamicSharedMemorySize, outln_smem);

    prep_kernel <<<1216, 256>>>(wq, wkv, wout, conv_w);        // 1
    kv_kernel   <<<PP, 256>>>(pattern);                        // 2
    convln_kernel<<<T / 32, 256, convln_smem>>>(x, conv_b, L); // 3
    dim3 ag(T / 32, HH);
    attn_kernel <<<ag, 256, attn_smem>>>();                    // 4 (profiled)
    outln_kernel<<<T / 32, 256, outln_smem>>>(bout, (float*)d_out); // 5
}

// round 13
// speedup vs baseline: 1.0649x; 1.0649x over previous
#include <cuda_runtime.h>
#include <cuda_bf16.h>

#define D    256
#define PP   512
#define HH   8
#define DA   64
#define TMAX 65536
typedef unsigned long long u64;
typedef unsigned int u32;
typedef unsigned short u16;

// ---------------- device scratch ----------------
__device__ float g_kt [HH * DA * PP];             // [h][d][p]
__device__ float g_v  [HH * PP * DA];             // [h][p][d]
__device__ float g_xn [(size_t)TMAX * D];
__device__ float g_att[(size_t)TMAX * 512];
__device__ float g_wqT[256 * 512];                // [k][j]
__device__ float g_woutP4[128 * 256 * 4];
__device__ float g_cwT [3 * D * D];
__device__ float g_wkvT[D * 1024];

// ---------------- f32x2 helpers ----------------
__device__ __forceinline__ u64 pack2(float x, float y) {
    u64 r; asm("mov.b64 %0,{%1,%2};" : "=l"(r) : "f"(x), "f"(y)); return r;
}
__device__ __forceinline__ u64 dup2(float x) { return pack2(x, x); }
__device__ __forceinline__ void fma2(u64& d, u64 a, u64 b) {
    asm("fma.rn.f32x2 %0,%1,%2,%0;" : "+l"(d) : "l"(a), "l"(b));
}
__device__ __forceinline__ float2 u2f(u64 v) {
    float2 f; asm("mov.b64 {%0,%1},%2;" : "=f"(f.x), "=f"(f.y) : "l"(v)); return f;
}

// ---------------- bf16 split + mma helpers ----------------
__device__ __forceinline__ void splitf(float v, u16& h, u16& l) {
    __nv_bfloat16 hb = __float2bfloat16(v);
    __nv_bfloat16 lb = __float2bfloat16(v - __bfloat162float(hb));
    h = __bfloat16_as_ushort(hb); l = __bfloat16_as_ushort(lb);
}
__device__ __forceinline__ u32 pckh(u16 a, u16 b) {
    u32 r; asm("mov.b32 %0,{%1,%2};" : "=r"(r) : "h"(a), "h"(b)); return r;
}
__device__ __forceinline__ u32 s2u(const void* p) {
    u32 a; asm("{ .reg .u64 t; cvta.to.shared.u64 t, %1; cvt.u32.u64 %0, t; }" : "=r"(a) : "l"(p));
    return a;
}
__device__ __forceinline__ void ldmA(u32* r, u32 a) {
    asm volatile("ldmatrix.sync.aligned.m8n8.x4.shared.b16 {%0,%1,%2,%3}, [%4];"
        : "=r"(r[0]), "=r"(r[1]), "=r"(r[2]), "=r"(r[3]) : "r"(a));
}
__device__ __forceinline__ void ldmB(u32* r, u32 a) {
    asm volatile("ldmatrix.sync.aligned.m8n8.x4.trans.shared.b16 {%0,%1,%2,%3}, [%4];"
        : "=r"(r[0]), "=r"(r[1]), "=r"(r[2]), "=r"(r[3]) : "r"(a));
}
__device__ __forceinline__ void mmabf(float* d, const u32* a, const u32* b) {
    asm volatile("mma.sync.aligned.m16n8k16.row.col.f32.bf16.bf16.f32 "
        "{%0,%1,%2,%3},{%4,%5,%6,%7},{%8,%9},{%0,%1,%2,%3};"
        : "+f"(d[0]), "+f"(d[1]), "+f"(d[2]), "+f"(d[3])
        : "r"(a[0]), "r"(a[1]), "r"(a[2]), "r"(a[3]), "r"(b[0]), "r"(b[1]));
}
// stage [64 rows][64 cols] fp32 -> hi/lo bf16 smem tiles, pitch 72 halves
__device__ __forceinline__ void stageHL(char* dH, char* dL, const float* src, int rstride, int tid) {
    int r = tid >> 2, cb = (tid & 3) << 4;
    const float* s = src + (size_t)r * rstride + cb;
    u16 h0, l0, h1, l1;
    #pragma unroll
    for (int i = 0; i < 16; i += 2) {
        splitf(s[i], h0, l0); splitf(s[i + 1], h1, l1);
        *(u32*)(dH + (r * 72 + cb + i) * 2) = pckh(h0, h1);
        *(u32*)(dL + (r * 72 + cb + i) * 2) = pckh(l0, l1);
    }
}

// ---------------- launch 1: weight reshapes (grid 1408 x 256) ----------------
__global__ void prep_kernel(const float* __restrict__ wq,
                            const float* __restrict__ wkv,
                            const float* __restrict__ wout,
                            const float* __restrict__ cw) {
    int bid = blockIdx.x, t = threadIdx.x;
    if (bid < 128) {
        int k4 = bid;
        #pragma unroll
        for (int kk = 0; kk < 4; kk++)
            g_woutP4[(k4 * 256 + t) * 4 + kk] = wout[t * 512 + 4 * k4 + kk];
    } else if (bid < 384) {
        int k = bid - 128;
        #pragma unroll
        for (int u = 0; u < 4; u++)
            g_wkvT[k * 1024 + t + u * 256] = wkv[(size_t)(t + u * 256) * 256 + k];
    } else if (bid < 1152) {
        int idx = bid - 384;
        int tap = idx >> 8, i = idx & 255;
        g_cwT[tap * 65536 + i * 256 + t] = cw[t * 768 + i * 3 + tap];
    } else {
        int k = bid - 1152;
        g_wqT[k * 512 + t]       = wq[t * 256 + k];
        g_wqT[k * 512 + t + 256] = wq[(t + 256) * 256 + k];
    }
}

// ---------------- launch 2: pattern double-LN + kv projection ----------------
__device__ __forceinline__ float block_reduce_sum256(float v, float* scratch) {
    #pragma unroll
    for (int o = 16; o; o >>= 1) v += __shfl_xor_sync(0xffffffffu, v, o);
    int w = threadIdx.x >> 5;
    if ((threadIdx.x & 31) == 0) scratch[w] = v;
    __syncthreads();
    if (threadIdx.x < 32) {
        float s = (threadIdx.x < 8) ? scratch[threadIdx.x] : 0.f;
        #pragma unroll
        for (int o = 4; o; o >>= 1) s += __shfl_xor_sync(0xffffffffu, s, o);
        if (threadIdx.x == 0) scratch[0] = s;
    }
    __syncthreads();
    float r = scratch[0];
    __syncthreads();
    return r;
}

__global__ void kv_kernel(const float* __restrict__ pattern) {
    __shared__ float scr[8];
    __shared__ float pr[D];
    int p = blockIdx.x, t = threadIdx.x;
    float v = pattern[p * D + t];
    #pragma unroll
    for (int rep = 0; rep < 2; rep++) {
        float s  = block_reduce_sum256(v, scr);
        float s2 = block_reduce_sum256(v * v, scr);
        float mu = s * (1.f / D);
        v = (v - mu) * rsqrtf(s2 * (1.f / D) - mu * mu + 1e-5f);
    }
    pr[t] = v;
    __syncthreads();
    float acc[4] = {0.f, 0.f, 0.f, 0.f};
    for (int i = 0; i < D; i++) {
        float xv = pr[i];
        const float* wr = g_wkvT + i * 1024 + t;
        #pragma unroll
        for (int u = 0; u < 4; u++) acc[u] = fmaf(xv, wr[u * 256], acc[u]);
    }
    #pragma unroll
    for (int u = 0; u < 4; u++) {
        int j = t + u * 256;
        int h = j >> 7, r = j & 127;
        if (r < DA) g_kt[((size_t)(h * 64) + r) * 512 + p] = acc[u];
        else        g_v [((size_t)(h * 512) + p) * 64 + (r - DA)] = acc[u];
    }
}

// ---------------- launch 3: conv + residual + leaky + LN ----------------
__global__ __launch_bounds__(256, 2) void convln_kernel(const float* __restrict__ x,
                                                        const float* __restrict__ conv_b,
                                                        int L) {
    extern __shared__ float sm[];
    float* xs = sm;
    float* ys = sm + 34 * D;
    float* st = ys + 32 * D;
    int tid = threadIdx.x;
    int c2 = tid & 127, th = tid >> 7;
    int t0 = blockIdx.x * 32;
    int pos0 = t0 % L;
    for (int r = 0; r < 34; r++) {
        float v = 0.f;
        if (pos0 + r >= 2) v = x[(size_t)(t0 + r - 2) * D + tid];
        xs[r * D + tid] = v;
    }
    __syncthreads();
    int m0 = th * 16;
    u64 acc[16];
    {
        float2 b = *(const float2*)&conv_b[2 * c2];
        u64 bp = pack2(b.x, b.y);
        #pragma unroll
        for (int j = 0; j < 16; j++) acc[j] = bp;
    }
    const float* cw0 = g_cwT + 2 * c2;
    for (int i = 0; i < D; i++) {
        u64 w0 = *(const u64*)(cw0 +           i * 256);
        u64 w1 = *(const u64*)(cw0 +  65536 + i * 256);
        u64 w2 = *(const u64*)(cw0 + 131072 + i * 256);
        u64 xa = dup2(xs[(m0)     * D + i]);
        u64 xb = dup2(xs[(m0 + 1) * D + i]);
        #pragma unroll
        for (int j = 0; j < 16; j++) {
            u64 xc = dup2(xs[(m0 + j + 2) * D + i]);
            fma2(acc[j], w0, xa); fma2(acc[j], w1, xb); fma2(acc[j], w2, xc);
            xa = xb; xb = xc;
        }
    }
    #pragma unroll
    for (int j = 0; j < 16; j++) {
        int m = m0 + j;
        float2 f = u2f(acc[j]);
        float2 res = *(const float2*)&xs[(m + 2) * D + 2 * c2];
        float v0 = f.x + res.x, v1 = f.y + res.y;
        v0 = v0 > 0.f ? v0 : 0.01f * v0;
        v1 = v1 > 0.f ? v1 : 0.01f * v1;
        *(float2*)&ys[m * D + 2 * c2] = make_float2(v0, v1);
    }
    __syncthreads();
    int lane = tid & 31, warp = tid >> 5;
    for (int jj = 0; jj < 4; jj++) {
        int m = warp + 8 * jj;
        float s = 0.f, s2 = 0.f;
        #pragma unroll
        for (int q = 0; q < 8; q++) {
            float v = ys[m * D + q * 32 + lane];
            s += v; s2 += v * v;
        }
        #pragma unroll
        for (int o = 16; o; o >>= 1) {
            s  += __shfl_xor_sync(0xffffffffu, s, o);
            s2 += __shfl_xor_sync(0xffffffffu, s2, o);
        }
        if (lane == 0) {
            float mu = s * (1.f / D);
            st[m] = mu;
            st[32 + m] = rsqrtf(s2 * (1.f / D) - mu * mu + 1e-5f);
        }
    }
    __syncthreads();
    #pragma unroll
    for (int m = 0; m < 32; m++)
        g_xn[(size_t)(t0 + m) * D + tid] = (ys[m * D + tid] - st[m]) * st[32 + m];
}

// ---------------- launch 4 (PROFILED): HMMA fused qproj + attention ----------------
// grid (T/64, 8), 256 threads (8 warps = 4 m-tiles x 2 n-halves).
// smem: QH@0 QL@9216 AH@18432 AL@27648 BH@36864 BL@46080 spart@55296 (55808 B)
__global__ __launch_bounds__(256) void attn_kernel() {
    extern __shared__ char smem[];
    const int QHo = 0, QLo = 9216, AHo = 18432, ALo = 27648, BHo = 36864, BLo = 46080;
    u32 sb = s2u(smem);
    int tid = threadIdx.x, lane = tid & 31, w = tid >> 5;
    int mt = w & 3, nh = w >> 2;
    int t0 = blockIdx.x * 64, h = blockIdx.y;
    float* spart = (float*)(smem + 55296);
    int lrow = lane & 15, lcol = (lane >> 4) << 3;

    // ---- qproj: Q[64 tok][64 j] = X @ WqT, 4 K-chunks ----
    float qD[4][4];
    #pragma unroll
    for (int i = 0; i < 4; i++)
        #pragma unroll
        for (int j = 0; j < 4; j++) qD[i][j] = 0.f;
    for (int c = 0; c < 4; c++) {
        __syncthreads();
        stageHL(smem + AHo, smem + ALo, g_xn + (size_t)t0 * D + c * 64, D, tid);
        stageHL(smem + BHo, smem + BLo, g_wqT + (size_t)(c * 64) * 512 + h * 64, 512, tid);
        __syncthreads();
        #pragma unroll
        for (int ks = 0; ks < 4; ks++) {
            int kb = ks * 16;
            u32 aH[4], aL[4];
            ldmA(aH, sb + AHo + ((mt * 16 + lrow) * 72 + kb + lcol) * 2);
            ldmA(aL, sb + ALo + ((mt * 16 + lrow) * 72 + kb + lcol) * 2);
            #pragma unroll
            for (int ng = 0; ng < 2; ng++) {
                int nb = nh * 32 + ng * 16;
                u32 bH[4], bL[4];
                ldmB(bH, sb + BHo + ((kb + lrow) * 72 + nb + lcol) * 2);
                ldmB(bL, sb + BLo + ((kb + lrow) * 72 + nb + lcol) * 2);
                #pragma unroll
                for (int ti = 0; ti < 2; ti++) {
                    u32 bh2[2] = {bH[2 * ti], bH[2 * ti + 1]};
                    u32 bl2[2] = {bL[2 * ti], bL[2 * ti + 1]};
                    float* dd = qD[ng * 2 + ti];
                    mmabf(dd, aH, bh2); mmabf(dd, aL, bh2); mmabf(dd, aH, bl2);
                }
            }
        }
    }
    __syncthreads();
    {   // store Q (split) into QH/QL
        int r0 = mt * 16 + (lane >> 2);
        #pragma unroll
        for (int nt = 0; nt < 4; nt++) {
            int c0 = nh * 32 + nt * 8 + 2 * (lane & 3);
            u16 h0, l0, h1, l1;
            splitf(qD[nt][0], h0, l0); splitf(qD[nt][1], h1, l1);
            *(u32*)(smem + QHo + (r0 * 72 + c0) * 2) = pckh(h0, h1);
            *(u32*)(smem + QLo + (r0 * 72 + c0) * 2) = pckh(l0, l1);
            splitf(qD[nt][2], h0, l0); splitf(qD[nt][3], h1, l1);
            *(u32*)(smem + QHo + ((r0 + 8) * 72 + c0) * 2) = pckh(h0, h1);
            *(u32*)(smem + QLo + ((r0 + 8) * 72 + c0) * 2) = pckh(l0, l1);
        }
    }

    // ---- 8 batches of 64 patterns: scores -> exp -> PV ----
    float pvD[4][4];
    #pragma unroll
    for (int i = 0; i < 4; i++)
        #pragma unroll
        for (int j = 0; j < 4; j++) pvD[i][j] = 0.f;
    float rs0 = 0.f, rs1 = 0.f;
    for (int b = 0; b < 8; b++) {
        __syncthreads();
        stageHL(smem + BHo, smem + BLo, g_kt + (size_t)(h * 64) * 512 + b * 64, 512, tid);
        __syncthreads();
        float sD[4][4];
        #pragma unroll
        for (int i = 0; i < 4; i++)
            #pragma unroll
            for (int j = 0; j < 4; j++) sD[i][j] = 0.f;
        #pragma unroll
        for (int ks = 0; ks < 4; ks++) {
            int kb = ks * 16;
            u32 aH[4], aL[4];
            ldmA(aH, sb + QHo + ((mt * 16 + lrow) * 72 + kb + lcol) * 2);
            ldmA(aL, sb + QLo + ((mt * 16 + lrow) * 72 + kb + lcol) * 2);
            #pragma unroll
            for (int ng = 0; ng < 2; ng++) {
                int nb = nh * 32 + ng * 16;
                u32 bH[4], bL[4];
                ldmB(bH, sb + BHo + ((kb + lrow) * 72 + nb + lcol) * 2);
                ldmB(bL, sb + BLo + ((kb + lrow) * 72 + nb + lcol) * 2);
                #pragma unroll
                for (int ti = 0; ti < 2; ti++) {
                    u32 bh2[2] = {bH[2 * ti], bH[2 * ti + 1]};
                    u32 bl2[2] = {bL[2 * ti], bL[2 * ti + 1]};
                    float* dd = sD[ng * 2 + ti];
                    mmabf(dd, aH, bh2); mmabf(dd, aL, bh2); mmabf(dd, aH, bl2);
                }
            }
        }
        // exp + split into A-buf (probs), accumulate row sums
        {
            int r0 = mt * 16 + (lane >> 2);
            #pragma unroll
            for (int nt = 0; nt < 4; nt++) {
                int c0 = nh * 32 + nt * 8 + 2 * (lane & 3);
                float e0 = __expf(0.125f * sD[nt][0]), e1 = __expf(0.125f * sD[nt][1]);
                float e2 = __expf(0.125f * sD[nt][2]), e3 = __expf(0.125f * sD[nt][3]);
                rs0 += e0 + e1; rs1 += e2 + e3;
                u16 h0, l0, h1, l1;
                splitf(e0, h0, l0); splitf(e1, h1, l1);
                *(u32*)(smem + AHo + (r0 * 72 + c0) * 2) = pckh(h0, h1);
                *(u32*)(smem + ALo + (r0 * 72 + c0) * 2) = pckh(l0, l1);
                splitf(e2, h0, l0); splitf(e3, h1, l1);
                *(u32*)(smem + AHo + ((r0 + 8) * 72 + c0) * 2) = pckh(h0, h1);
                *(u32*)(smem + ALo + ((r0 + 8) * 72 + c0) * 2) = pckh(l0, l1);
            }
        }
        __syncthreads();
        stageHL(smem + BHo, smem + BLo, g_v + ((size_t)(h * 512) + b * 64) * 64, 64, tid);
        __syncthreads();
        #pragma unroll
        for (int ks = 0; ks < 4; ks++) {
            int kb = ks * 16;
            u32 aH[4], aL[4];
            ldmA(aH, sb + AHo + ((mt * 16 + lrow) * 72 + kb + lcol) * 2);
            ldmA(aL, sb + ALo + ((mt * 16 + lrow) * 72 + kb + lcol) * 2);
            #pragma unroll
            for (int ng = 0; ng < 2; ng++) {
                int nb = nh * 32 + ng * 16;
                u32 bH[4], bL[4];
                ldmB(bH, sb + BHo + ((kb + lrow) * 72 + nb + lcol) * 2);
                ldmB(bL, sb + BLo + ((kb + lrow) * 72 + nb + lcol) * 2);
                #pragma unroll
                for (int ti = 0; ti < 2; ti++) {
                    u32 bh2[2] = {bH[2 * ti], bH[2 * ti + 1]};
                    u32 bl2[2] = {bL[2 * ti], bL[2 * ti + 1]};
                    float* dd = pvD[ng * 2 + ti];
                    mmabf(dd, aH, bh2); mmabf(dd, aL, bh2); mmabf(dd, aH, bl2);
                }
            }
        }
    }
    // row sums: reduce over lane quads, publish per (nh, row)
    rs0 += __shfl_xor_sync(0xffffffffu, rs0, 1);
    rs0 += __shfl_xor_sync(0xffffffffu, rs0, 2);
    rs1 += __shfl_xor_sync(0xffffffffu, rs1, 1);
    rs1 += __shfl_xor_sync(0xffffffffu, rs1, 2);
    if ((lane & 3) == 0) {
        spart[nh * 64 + mt * 16 + (lane >> 2)]     = rs0;
        spart[nh * 64 + mt * 16 + 8 + (lane >> 2)] = rs1;
    }
    __syncthreads();
    {   // normalize + store
        int r0 = mt * 16 + (lane >> 2);
        float ri0 = 1.f / (spart[r0] + spart[64 + r0]);
        float ri1 = 1.f / (spart[r0 + 8] + spart[64 + r0 + 8]);
        #pragma unroll
        for (int nt = 0; nt < 4; nt++) {
            int c0 = nh * 32 + nt * 8 + 2 * (lane & 3);
            *(float2*)(g_att + (size_t)(t0 + r0) * 512 + h * 64 + c0) =
                make_float2(pvD[nt][0] * ri0, pvD[nt][1] * ri0);
            *(float2*)(g_att + (size_t)(t0 + r0 + 8) * 512 + h * 64 + c0) =
                make_float2(pvD[nt][2] * ri1, pvD[nt][3] * ri1);
        }
    }
}

// ---------------- launch 5: out projection + final LN ----------------
__global__ __launch_bounds__(256, 2) void outln_kernel(const float* __restrict__ bout,
                                                       float* __restrict__ out) {
    extern __shared__ float sm[];
    float* as_ = sm;             // [32][516]
    int tid = threadIdx.x, lane = tid & 31, w = tid >> 5;
    int t0 = blockIdx.x * 32;
    {
        int tok = tid >> 3, q0 = tid & 7;
        const float4* src = (const float4*)&g_att[(size_t)(t0 + tok) * 512];
        float4* dst = (float4*)&as_[tok * 516];
        #pragma unroll
        for (int i = 0; i < 16; i++) dst[q0 + 8 * i] = src[q0 + 8 * i];
    }
    __syncthreads();
    u64 acc[4][8];
    #pragma unroll
    for (int tt = 0; tt < 4; tt++)
        #pragma unroll
        for (int j = 0; j < 8; j++) acc[tt][j] = 0;
    const float* wb = g_woutP4 + lane * 4;
    for (int k4 = 0; k4 < 128; k4++) {
        const float* wr = wb + k4 * 1024;
        ulonglong2 B[8];
        #pragma unroll
        for (int j = 0; j < 8; j++) B[j] = *(const ulonglong2*)(wr + j * 128);
        #pragma unroll
        for (int tt = 0; tt < 4; tt++) {
            ulonglong2 A = *(const ulonglong2*)&as_[(4 * w + tt) * 516 + 4 * k4];
            #pragma unroll
            for (int j = 0; j < 8; j++) {
                fma2(acc[tt][j], A.x, B[j].x);
                fma2(acc[tt][j], A.y, B[j].y);
            }
        }
    }
    #pragma unroll
    for (int tt = 0; tt < 4; tt++) {
        int tok = 4 * w + tt;
        float vals[8];
        float s = 0.f, s2 = 0.f;
        #pragma unroll
        for (int j = 0; j < 8; j++) {
            float2 f = u2f(acc[tt][j]);
            float v = f.x + f.y + __ldg(&bout[lane + 32 * j]);
            vals[j] = v;
            s += v; s2 += v * v;
        }
        #pragma unroll
        for (int o = 16; o; o >>= 1) {
            s  += __shfl_xor_sync(0xffffffffu, s, o);
            s2 += __shfl_xor_sync(0xffffffffu, s2, o);
        }
        float mu = s * (1.f / D);
        float rstd = rsqrtf(s2 * (1.f / D) - mu * mu + 1e-5f);
        #pragma unroll
        for (int j = 0; j < 8; j++)
            out[(size_t)(t0 + tok) * D + lane + 32 * j] = (vals[j] - mu) * rstd;
    }
}

// ---------------- launch ----------------
extern "C" void kernel_launch(void* const* d_in, const int* in_sizes, int n_in,
                              void* d_out, int out_size) {
    const float* x       = (const float*)d_in[0];
    const float* conv_w  = (const float*)d_in[1];
    const float* conv_b  = (const float*)d_in[2];
    const float* pattern = (const float*)d_in[3];
    const float* wq      = (const float*)d_in[4];
    const float* wkv     = (const float*)d_in[5];
    const float* wout    = (const float*)d_in[6];
    const float* bout    = (const float*)d_in[7];

    int T = in_sizes[0] / D;
    int B = in_sizes[8] - 1;
    int L = T / B;

    int convln_smem = (34 * D + 32 * D + 64) * 4;   // 67840
    int outln_smem  = (32 * 516) * 4;               // 66048
    int attn_smem   = 55808;
    cudaFuncSetAttribute(convln_kernel, cudaFuncAttributeMaxDynamicSharedMemorySize, convln_smem);
    cudaFuncSetAttribute(outln_kernel,  cudaFuncAttributeMaxDynamicSharedMemorySize, outln_smem);
    cudaFuncSetAttribute(attn_kernel,   cudaFuncAttributeMaxDynamicSharedMemorySize, attn_smem);

    prep_kernel <<<1408, 256>>>(wq, wkv, wout, conv_w);        // 1
    kv_kernel   <<<PP, 256>>>(pattern);                        // 2
    convln_kernel<<<T / 32, 256, convln_smem>>>(x, conv_b, L); // 3
    dim3 ag(T / 64, HH);
    attn_kernel <<<ag, 256, attn_smem>>>();                    // 4 (profiled)
    outln_kernel<<<T / 32, 256, outln_smem>>>(bout, (float*)d_out); // 5
}

// round 14
// speedup vs baseline: 1.7544x; 1.6475x over previous
#include <cuda_runtime.h>
#include <cuda_bf16.h>

#define D    256
#define PP   512
#define HH   8
#define DA   64
#define TMAX 65536
typedef unsigned long long u64;
typedef unsigned int u32;
typedef unsigned short u16;

// ---------------- device scratch ----------------
__device__ __align__(16) __nv_bfloat16 g_ktH[HH * DA * PP];   // [h][d][p]
__device__ __align__(16) __nv_bfloat16 g_ktL[HH * DA * PP];
__device__ __align__(16) __nv_bfloat16 g_vH [HH * PP * DA];   // [h][p][d]
__device__ __align__(16) __nv_bfloat16 g_vL [HH * PP * DA];
__device__ __align__(16) __nv_bfloat16 g_xnH[(size_t)TMAX * D];
__device__ __align__(16) __nv_bfloat16 g_xnL[(size_t)TMAX * D];
__device__ __align__(16) __nv_bfloat16 g_wqTH[256 * 512];     // [k][j]
__device__ __align__(16) __nv_bfloat16 g_wqTL[256 * 512];
__device__ float g_att[(size_t)TMAX * 512];
__device__ float g_woutP4[128 * 256 * 4];
__device__ float g_cwT [3 * D * D];
__device__ float g_wkvT[D * 1024];

// ---------------- f32x2 helpers ----------------
__device__ __forceinline__ u64 pack2(float x, float y) {
    u64 r; asm("mov.b64 %0,{%1,%2};" : "=l"(r) : "f"(x), "f"(y)); return r;
}
__device__ __forceinline__ u64 dup2(float x) { return pack2(x, x); }
__device__ __forceinline__ void fma2(u64& d, u64 a, u64 b) {
    asm("fma.rn.f32x2 %0,%1,%2,%0;" : "+l"(d) : "l"(a), "l"(b));
}
__device__ __forceinline__ float2 u2f(u64 v) {
    float2 f; asm("mov.b64 {%0,%1},%2;" : "=f"(f.x), "=f"(f.y) : "l"(v)); return f;
}

// ---------------- bf16 split + mma helpers ----------------
__device__ __forceinline__ void splitf(float v, u16& h, u16& l) {
    __nv_bfloat16 hb = __float2bfloat16(v);
    __nv_bfloat16 lb = __float2bfloat16(v - __bfloat162float(hb));
    h = __bfloat16_as_ushort(hb); l = __bfloat16_as_ushort(lb);
}
__device__ __forceinline__ u32 pckh(u16 a, u16 b) {
    u32 r; asm("mov.b32 %0,{%1,%2};" : "=r"(r) : "h"(a), "h"(b)); return r;
}
__device__ __forceinline__ u32 s2u(const void* p) {
    u32 a; asm("{ .reg .u64 t; cvta.to.shared.u64 t, %1; cvt.u32.u64 %0, t; }" : "=r"(a) : "l"(p));
    return a;
}
__device__ __forceinline__ void ldmA(u32* r, u32 a) {
    asm volatile("ldmatrix.sync.aligned.m8n8.x4.shared.b16 {%0,%1,%2,%3}, [%4];"
        : "=r"(r[0]), "=r"(r[1]), "=r"(r[2]), "=r"(r[3]) : "r"(a));
}
__device__ __forceinline__ void ldmB(u32* r, u32 a) {
    asm volatile("ldmatrix.sync.aligned.m8n8.x4.trans.shared.b16 {%0,%1,%2,%3}, [%4];"
        : "=r"(r[0]), "=r"(r[1]), "=r"(r[2]), "=r"(r[3]) : "r"(a));
}
__device__ __forceinline__ void mmabf(float* d, const u32* a, const u32* b) {
    asm volatile("mma.sync.aligned.m16n8k16.row.col.f32.bf16.bf16.f32 "
        "{%0,%1,%2,%3},{%4,%5,%6,%7},{%8,%9},{%0,%1,%2,%3};"
        : "+f"(d[0]), "+f"(d[1]), "+f"(d[2]), "+f"(d[3])
        : "r"(a[0]), "r"(a[1]), "r"(a[2]), "r"(a[3]), "r"(b[0]), "r"(b[1]));
}
// copy a [64 rows][64 cols] bf16 tile (row pitch rstride halves) -> smem pitch-72
__device__ __forceinline__ void stageB16(char* dst, const __nv_bfloat16* src, int rstride, int tid) {
    int r = tid >> 2, cb = (tid & 3) << 4;
    const uint4* s = (const uint4*)(src + (size_t)r * rstride + cb);
    uint4* d = (uint4*)(dst + (r * 72 + cb) * 2);
    d[0] = s[0]; d[1] = s[1];
}

// ---------------- launch 1: weight reshapes (grid 1408 x 256) ----------------
__global__ void prep_kernel(const float* __restrict__ wq,
                            const float* __restrict__ wkv,
                            const float* __restrict__ wout,
                            const float* __restrict__ cw) {
    int bid = blockIdx.x, t = threadIdx.x;
    if (bid < 128) {
        int k4 = bid;
        #pragma unroll
        for (int kk = 0; kk < 4; kk++)
            g_woutP4[(k4 * 256 + t) * 4 + kk] = wout[t * 512 + 4 * k4 + kk];
    } else if (bid < 384) {
        int k = bid - 128;
        #pragma unroll
        for (int u = 0; u < 4; u++)
            g_wkvT[k * 1024 + t + u * 256] = wkv[(size_t)(t + u * 256) * 256 + k];
    } else if (bid < 1152) {
        int idx = bid - 384;
        int tap = idx >> 8, i = idx & 255;
        g_cwT[tap * 65536 + i * 256 + t] = cw[t * 768 + i * 3 + tap];
    } else {
        int k = bid - 1152;
        u16 h0, l0;
        splitf(wq[t * 256 + k], h0, l0);
        g_wqTH[k * 512 + t] = __ushort_as_bfloat16(h0);
        g_wqTL[k * 512 + t] = __ushort_as_bfloat16(l0);
        splitf(wq[(t + 256) * 256 + k], h0, l0);
        g_wqTH[k * 512 + t + 256] = __ushort_as_bfloat16(h0);
        g_wqTL[k * 512 + t + 256] = __ushort_as_bfloat16(l0);
    }
}

// ---------------- launch 2: pattern double-LN + kv projection ----------------
__device__ __forceinline__ float block_reduce_sum256(float v, float* scratch) {
    #pragma unroll
    for (int o = 16; o; o >>= 1) v += __shfl_xor_sync(0xffffffffu, v, o);
    int w = threadIdx.x >> 5;
    if ((threadIdx.x & 31) == 0) scratch[w] = v;
    __syncthreads();
    if (threadIdx.x < 32) {
        float s = (threadIdx.x < 8) ? scratch[threadIdx.x] : 0.f;
        #pragma unroll
        for (int o = 4; o; o >>= 1) s += __shfl_xor_sync(0xffffffffu, s, o);
        if (threadIdx.x == 0) scratch[0] = s;
    }
    __syncthreads();
    float r = scratch[0];
    __syncthreads();
    return r;
}

__global__ void kv_kernel(const float* __restrict__ pattern) {
    __shared__ float scr[8];
    __shared__ float pr[D];
    int p = blockIdx.x, t = threadIdx.x;
    float v = pattern[p * D + t];
    #pragma unroll
    for (int rep = 0; rep < 2; rep++) {
        float s  = block_reduce_sum256(v, scr);
        float s2 = block_reduce_sum256(v * v, scr);
        float mu = s * (1.f / D);
        v = (v - mu) * rsqrtf(s2 * (1.f / D) - mu * mu + 1e-5f);
    }
    pr[t] = v;
    __syncthreads();
    float acc[4] = {0.f, 0.f, 0.f, 0.f};
    for (int i = 0; i < D; i++) {
        float xv = pr[i];
        const float* wr = g_wkvT + i * 1024 + t;
        #pragma unroll
        for (int u = 0; u < 4; u++) acc[u] = fmaf(xv, wr[u * 256], acc[u]);
    }
    #pragma unroll
    for (int u = 0; u < 4; u++) {
        int j = t + u * 256;
        int h = j >> 7, r = j & 127;
        u16 hi, lo; splitf(acc[u], hi, lo);
        if (r < DA) {
            g_ktH[((size_t)(h * 64) + r) * 512 + p] = __ushort_as_bfloat16(hi);
            g_ktL[((size_t)(h * 64) + r) * 512 + p] = __ushort_as_bfloat16(lo);
        } else {
            g_vH[((size_t)(h * 512) + p) * 64 + (r - DA)] = __ushort_as_bfloat16(hi);
            g_vL[((size_t)(h * 512) + p) * 64 + (r - DA)] = __ushort_as_bfloat16(lo);
        }
    }
}

// ---------------- launch 3: conv + residual + leaky + LN -> split bf16 ----------------
__global__ __launch_bounds__(256, 2) void convln_kernel(const float* __restrict__ x,
                                                        const float* __restrict__ conv_b,
                                                        int L) {
    extern __shared__ float sm[];
    float* xs = sm;
    float* ys = sm + 34 * D;
    float* st = ys + 32 * D;
    int tid = threadIdx.x;
    int c2 = tid & 127, th = tid >> 7;
    int t0 = blockIdx.x * 32;
    int pos0 = t0 % L;
    for (int r = 0; r < 34; r++) {
        float v = 0.f;
        if (pos0 + r >= 2) v = x[(size_t)(t0 + r - 2) * D + tid];
        xs[r * D + tid] = v;
    }
    __syncthreads();
    int m0 = th * 16;
    u64 acc[16];
    {
        float2 b = *(const float2*)&conv_b[2 * c2];
        u64 bp = pack2(b.x, b.y);
        #pragma unroll
        for (int j = 0; j < 16; j++) acc[j] = bp;
    }
    const float* cw0 = g_cwT + 2 * c2;
    for (int i = 0; i < D; i++) {
        u64 w0 = *(const u64*)(cw0 +           i * 256);
        u64 w1 = *(const u64*)(cw0 +  65536 + i * 256);
        u64 w2 = *(const u64*)(cw0 + 131072 + i * 256);
        u64 xa = dup2(xs[(m0)     * D + i]);
        u64 xb = dup2(xs[(m0 + 1) * D + i]);
        #pragma unroll
        for (int j = 0; j < 16; j++) {
            u64 xc = dup2(xs[(m0 + j + 2) * D + i]);
            fma2(acc[j], w0, xa); fma2(acc[j], w1, xb); fma2(acc[j], w2, xc);
            xa = xb; xb = xc;
        }
    }
    #pragma unroll
    for (int j = 0; j < 16; j++) {
        int m = m0 + j;
        float2 f = u2f(acc[j]);
        float2 res = *(const float2*)&xs[(m + 2) * D + 2 * c2];
        float v0 = f.x + res.x, v1 = f.y + res.y;
        v0 = v0 > 0.f ? v0 : 0.01f * v0;
        v1 = v1 > 0.f ? v1 : 0.01f * v1;
        *(float2*)&ys[m * D + 2 * c2] = make_float2(v0, v1);
    }
    __syncthreads();
    int lane = tid & 31, warp = tid >> 5;
    for (int jj = 0; jj < 4; jj++) {
        int m = warp + 8 * jj;
        float s = 0.f, s2 = 0.f;
        #pragma unroll
        for (int q = 0; q < 8; q++) {
            float v = ys[m * D + q * 32 + lane];
            s += v; s2 += v * v;
        }
        #pragma unroll
        for (int o = 16; o; o >>= 1) {
            s  += __shfl_xor_sync(0xffffffffu, s, o);
            s2 += __shfl_xor_sync(0xffffffffu, s2, o);
        }
        if (lane == 0) {
            float mu = s * (1.f / D);
            st[m] = mu;
            st[32 + m] = rsqrtf(s2 * (1.f / D) - mu * mu + 1e-5f);
        }
    }
    __syncthreads();
    #pragma unroll
    for (int m = 0; m < 32; m++) {
        float v = (ys[m * D + tid] - st[m]) * st[32 + m];
        u16 hi, lo; splitf(v, hi, lo);
        g_xnH[(size_t)(t0 + m) * D + tid] = __ushort_as_bfloat16(hi);
        g_xnL[(size_t)(t0 + m) * D + tid] = __ushort_as_bfloat16(lo);
    }
}

// ---------------- launch 4 (PROFILED): HMMA fused qproj + attention ----------------
// grid (T/64, 8), 256 threads (8 warps = 4 m-tiles x 2 n-halves).
// smem: QH@0 QL@9216 AH@18432 AL@27648 BH@36864 BL@46080 VH@55296 VL@64512 spart@73728 (74240 B)
__global__ __launch_bounds__(256) void attn_kernel() {
    extern __shared__ char smem[];
    const int QHo = 0, QLo = 9216, AHo = 18432, ALo = 27648, BHo = 36864, BLo = 46080,
              VHo = 55296, VLo = 64512;
    u32 sb = s2u(smem);
    int tid = threadIdx.x, lane = tid & 31, w = tid >> 5;
    int mt = w & 3, nh = w >> 2;
    int t0 = blockIdx.x * 64, h = blockIdx.y;
    float* spart = (float*)(smem + 73728);
    int lrow = lane & 15, lcol = (lane >> 4) << 3;

    // ---- qproj: Q[64 tok][64 j] = X @ WqT, 4 K-chunks ----
    float qD[4][4];
    #pragma unroll
    for (int i = 0; i < 4; i++)
        #pragma unroll
        for (int j = 0; j < 4; j++) qD[i][j] = 0.f;
    for (int c = 0; c < 4; c++) {
        __syncthreads();
        stageB16(smem + AHo, g_xnH + (size_t)t0 * D + c * 64, D, tid);
        stageB16(smem + ALo, g_xnL + (size_t)t0 * D + c * 64, D, tid);
        stageB16(smem + BHo, g_wqTH + (size_t)(c * 64) * 512 + h * 64, 512, tid);
        stageB16(smem + BLo, g_wqTL + (size_t)(c * 64) * 512 + h * 64, 512, tid);
        __syncthreads();
        #pragma unroll
        for (int ks = 0; ks < 4; ks++) {
            int kb = ks * 16;
            u32 aH[4], aL[4];
            ldmA(aH, sb + AHo + ((mt * 16 + lrow) * 72 + kb + lcol) * 2);
            ldmA(aL, sb + ALo + ((mt * 16 + lrow) * 72 + kb + lcol) * 2);
            #pragma unroll
            for (int ng = 0; ng < 2; ng++) {
                int nb = nh * 32 + ng * 16;
                u32 bH[4], bL[4];
                ldmB(bH, sb + BHo + ((kb + lrow) * 72 + nb + lcol) * 2);
                ldmB(bL, sb + BLo + ((kb + lrow) * 72 + nb + lcol) * 2);
                #pragma unroll
                for (int ti = 0; ti < 2; ti++) {
                    u32 bh2[2] = {bH[2 * ti], bH[2 * ti + 1]};
                    u32 bl2[2] = {bL[2 * ti], bL[2 * ti + 1]};
                    float* dd = qD[ng * 2 + ti];
                    mmabf(dd, aH, bh2); mmabf(dd, aL, bh2); mmabf(dd, aH, bl2);
                }
            }
        }
    }
    __syncthreads();
    {   // store Q (split) into QH/QL
        int r0 = mt * 16 + (lane >> 2);
        #pragma unroll
        for (int nt = 0; nt < 4; nt++) {
            int c0 = nh * 32 + nt * 8 + 2 * (lane & 3);
            u16 h0, l0, h1, l1;
            splitf(qD[nt][0], h0, l0); splitf(qD[nt][1], h1, l1);
            *(u32*)(smem + QHo + (r0 * 72 + c0) * 2) = pckh(h0, h1);
            *(u32*)(smem + QLo + (r0 * 72 + c0) * 2) = pckh(l0, l1);
            splitf(qD[nt][2], h0, l0); splitf(qD[nt][3], h1, l1);
            *(u32*)(smem + QHo + ((r0 + 8) * 72 + c0) * 2) = pckh(h0, h1);
            *(u32*)(smem + QLo + ((r0 + 8) * 72 + c0) * 2) = pckh(l0, l1);
        }
    }

    // ---- 8 batches of 64 patterns: scores -> exp -> PV ----
    float pvD[4][4];
    #pragma unroll
    for (int i = 0; i < 4; i++)
        #pragma unroll
        for (int j = 0; j < 4; j++) pvD[i][j] = 0.f;
    float rs0 = 0.f, rs1 = 0.f;
    for (int b = 0; b < 8; b++) {
        __syncthreads();
        stageB16(smem + BHo, g_ktH + (size_t)(h * 64) * 512 + b * 64, 512, tid);
        stageB16(smem + BLo, g_ktL + (size_t)(h * 64) * 512 + b * 64, 512, tid);
        stageB16(smem + VHo, g_vH + ((size_t)(h * 512) + b * 64) * 64, 64, tid);
        stageB16(smem + VLo, g_vL + ((size_t)(h * 512) + b * 64) * 64, 64, tid);
        __syncthreads();
        float sD[4][4];
        #pragma unroll
        for (int i = 0; i < 4; i++)
            #pragma unroll
            for (int j = 0; j < 4; j++) sD[i][j] = 0.f;
        #pragma unroll
        for (int ks = 0; ks < 4; ks++) {
            int kb = ks * 16;
            u32 aH[4], aL[4];
            ldmA(aH, sb + QHo + ((mt * 16 + lrow) * 72 + kb + lcol) * 2);
            ldmA(aL, sb + QLo + ((mt * 16 + lrow) * 72 + kb + lcol) * 2);
            #pragma unroll
            for (int ng = 0; ng < 2; ng++) {
                int nb = nh * 32 + ng * 16;
                u32 bH[4], bL[4];
                ldmB(bH, sb + BHo + ((kb + lrow) * 72 + nb + lcol) * 2);
                ldmB(bL, sb + BLo + ((kb + lrow) * 72 + nb + lcol) * 2);
                #pragma unroll
                for (int ti = 0; ti < 2; ti++) {
                    u32 bh2[2] = {bH[2 * ti], bH[2 * ti + 1]};
                    u32 bl2[2] = {bL[2 * ti], bL[2 * ti + 1]};
                    float* dd = sD[ng * 2 + ti];
                    mmabf(dd, aH, bh2); mmabf(dd, aL, bh2); mmabf(dd, aH, bl2);
                }
            }
        }
        {   // exp + split into A-buf (probs), accumulate row sums
            int r0 = mt * 16 + (lane >> 2);
            #pragma unroll
            for (int nt = 0; nt < 4; nt++) {
                int c0 = nh * 32 + nt * 8 + 2 * (lane & 3);
                float e0 = __expf(0.125f * sD[nt][0]), e1 = __expf(0.125f * sD[nt][1]);
                float e2 = __expf(0.125f * sD[nt][2]), e3 = __expf(0.125f * sD[nt][3]);
                rs0 += e0 + e1; rs1 += e2 + e3;
                u16 h0, l0, h1, l1;
                splitf(e0, h0, l0); splitf(e1, h1, l1);
                *(u32*)(smem + AHo + (r0 * 72 + c0) * 2) = pckh(h0, h1);
                *(u32*)(smem + ALo + (r0 * 72 + c0) * 2) = pckh(l0, l1);
                splitf(e2, h0, l0); splitf(e3, h1, l1);
                *(u32*)(smem + AHo + ((r0 + 8) * 72 + c0) * 2) = pckh(h0, h1);
                *(u32*)(smem + ALo + ((r0 + 8) * 72 + c0) * 2) = pckh(l0, l1);
            }
        }
        __syncthreads();
        #pragma unroll
        for (int ks = 0; ks < 4; ks++) {
            int kb = ks * 16;
            u32 aH[4], aL[4];
            ldmA(aH, sb + AHo + ((mt * 16 + lrow) * 72 + kb + lcol) * 2);
            ldmA(aL, sb + ALo + ((mt * 16 + lrow) * 72 + kb + lcol) * 2);
            #pragma unroll
            for (int ng = 0; ng < 2; ng++) {
                int nb = nh * 32 + ng * 16;
                u32 bH[4], bL[4];
                ldmB(bH, sb + VHo + ((kb + lrow) * 72 + nb + lcol) * 2);
                ldmB(bL, sb + VLo + ((kb + lrow) * 72 + nb + lcol) * 2);
                #pragma unroll
                for (int ti = 0; ti < 2; ti++) {
                    u32 bh2[2] = {bH[2 * ti], bH[2 * ti + 1]};
                    u32 bl2[2] = {bL[2 * ti], bL[2 * ti + 1]};
                    float* dd = pvD[ng * 2 + ti];
                    mmabf(dd, aH, bh2); mmabf(dd, aL, bh2); mmabf(dd, aH, bl2);
                }
            }
        }
    }
    // row sums: reduce over lane quads, publish per (nh, row)
    rs0 += __shfl_xor_sync(0xffffffffu, rs0, 1);
    rs0 += __shfl_xor_sync(0xffffffffu, rs0, 2);
    rs1 += __shfl_xor_sync(0xffffffffu, rs1, 1);
    rs1 += __shfl_xor_sync(0xffffffffu, rs1, 2);
    if ((lane & 3) == 0) {
        spart[nh * 64 + mt * 16 + (lane >> 2)]     = rs0;
        spart[nh * 64 + mt * 16 + 8 + (lane >> 2)] = rs1;
    }
    __syncthreads();
    {   // normalize + store
        int r0 = mt * 16 + (lane >> 2);
        float ri0 = 1.f / (spart[r0] + spart[64 + r0]);
        float ri1 = 1.f / (spart[r0 + 8] + spart[64 + r0 + 8]);
        #pragma unroll
        for (int nt = 0; nt < 4; nt++) {
            int c0 = nh * 32 + nt * 8 + 2 * (lane & 3);
            *(float2*)(g_att + (size_t)(t0 + r0) * 512 + h * 64 + c0) =
                make_float2(pvD[nt][0] * ri0, pvD[nt][1] * ri0);
            *(float2*)(g_att + (size_t)(t0 + r0 + 8) * 512 + h * 64 + c0) =
                make_float2(pvD[nt][2] * ri1, pvD[nt][3] * ri1);
        }
    }
}

// ---------------- launch 5: out projection + final LN ----------------
__global__ __launch_bounds__(256, 2) void outln_kernel(const float* __restrict__ bout,
                                                       float* __restrict__ out) {
    extern __shared__ float sm[];
    float* as_ = sm;             // [32][516]
    int tid = threadIdx.x, lane = tid & 31, w = tid >> 5;
    int t0 = blockIdx.x * 32;
    {
        int tok = tid >> 3, q0 = tid & 7;
        const float4* src = (const float4*)&g_att[(size_t)(t0 + tok) * 512];
        float4* dst = (float4*)&as_[tok * 516];
        #pragma unroll
        for (int i = 0; i < 16; i++) dst[q0 + 8 * i] = src[q0 + 8 * i];
    }
    __syncthreads();
    u64 acc[4][8];
    #pragma unroll
    for (int tt = 0; tt < 4; tt++)
        #pragma unroll
        for (int j = 0; j < 8; j++) acc[tt][j] = 0;
    const float* wb = g_woutP4 + lane * 4;
    for (int k4 = 0; k4 < 128; k4++) {
        const float* wr = wb + k4 * 1024;
        ulonglong2 B[8];
        #pragma unroll
        for (int j = 0; j < 8; j++) B[j] = *(const ulonglong2*)(wr + j * 128);
        #pragma unroll
        for (int tt = 0; tt < 4; tt++) {
            ulonglong2 A = *(const ulonglong2*)&as_[(4 * w + tt) * 516 + 4 * k4];
            #pragma unroll
            for (int j = 0; j < 8; j++) {
                fma2(acc[tt][j], A.x, B[j].x);
                fma2(acc[tt][j], A.y, B[j].y);
            }
        }
    }
    #pragma unroll
    for (int tt = 0; tt < 4; tt++) {
        int tok = 4 * w + tt;
        float vals[8];
        float s = 0.f, s2 = 0.f;
        #pragma unroll
        for (int j = 0; j < 8; j++) {
            float2 f = u2f(acc[tt][j]);
            float v = f.x + f.y + __ldg(&bout[lane + 32 * j]);
            vals[j] = v;
            s += v; s2 += v * v;
        }
        #pragma unroll
        for (int o = 16; o; o >>= 1) {
            s  += __shfl_xor_sync(0xffffffffu, s, o);
            s2 += __shfl_xor_sync(0xffffffffu, s2, o);
        }
        float mu = s * (1.f / D);
        float rstd = rsqrtf(s2 * (1.f / D) - mu * mu + 1e-5f);
        #pragma unroll
        for (int j = 0; j < 8; j++)
            out[(size_t)(t0 + tok) * D + lane + 32 * j] = (vals[j] - mu) * rstd;
    }
}

// ---------------- launch ----------------
extern "C" void kernel_launch(void* const* d_in, const int* in_sizes, int n_in,
                              void* d_out, int out_size) {
    const float* x       = (const float*)d_in[0];
    const float* conv_w  = (const float*)d_in[1];
    const float* conv_b  = (const float*)d_in[2];
    const float* pattern = (const float*)d_in[3];
    const float* wq      = (const float*)d_in[4];
    const float* wkv     = (const float*)d_in[5];
    const float* wout    = (const float*)d_in[6];
    const float* bout    = (const float*)d_in[7];

    int T = in_sizes[0] / D;
    int B = in_sizes[8] - 1;
    int L = T / B;

    int convln_smem = (34 * D + 32 * D + 64) * 4;   // 67840
    int outln_smem  = (32 * 516) * 4;               // 66048
    int attn_smem   = 74240;
    cudaFuncSetAttribute(convln_kernel, cudaFuncAttributeMaxDynamicSharedMemorySize, convln_smem);
    cudaFuncSetAttribute(outln_kernel,  cudaFuncAttributeMaxDynamicSharedMemorySize, outln_smem);
    cudaFuncSetAttribute(attn_kernel,   cudaFuncAttributeMaxDynamicSharedMemorySize, attn_smem);

    prep_kernel <<<1408, 256>>>(wq, wkv, wout, conv_w);        // 1
    kv_kernel   <<<PP, 256>>>(pattern);                        // 2
    convln_kernel<<<T / 32, 256, convln_smem>>>(x, conv_b, L); // 3
    dim3 ag(T / 64, HH);
    attn_kernel <<<ag, 256, attn_smem>>>();                    // 4 (profiled)
    outln_kernel<<<T / 32, 256, outln_smem>>>(bout, (float*)d_out); // 5
}

// round 15
// speedup vs baseline: 2.2414x; 1.2776x over previous
#include <cuda_runtime.h>
#include <cuda_bf16.h>

#define D    256
#define PP   512
#define HH   8
#define DA   64
#define TMAX 65536
typedef unsigned long long u64;
typedef unsigned int u32;
typedef unsigned short u16;

// ---------------- device scratch ----------------
__device__ __align__(16) __nv_bfloat16 g_ktH[HH * DA * PP];   // [h][d][p]
__device__ __align__(16) __nv_bfloat16 g_ktL[HH * DA * PP];
__device__ __align__(16) __nv_bfloat16 g_vH [HH * PP * DA];   // [h][p][d]
__device__ __align__(16) __nv_bfloat16 g_vL [HH * PP * DA];
__device__ __align__(16) __nv_bfloat16 g_xnH[(size_t)TMAX * D];
__device__ __align__(16) __nv_bfloat16 g_xnL[(size_t)TMAX * D];
__device__ __align__(16) __nv_bfloat16 g_attH[(size_t)TMAX * 512];
__device__ __align__(16) __nv_bfloat16 g_attL[(size_t)TMAX * 512];
__device__ __align__(16) __nv_bfloat16 g_wqTH[256 * 512];     // [k][j]
__device__ __align__(16) __nv_bfloat16 g_wqTL[256 * 512];
__device__ uint4 g_cwF[48 * 32 * 32];    // conv W frags [ks][n8][lane]
__device__ uint4 g_woF[32 * 32 * 32];    // wout frags
__device__ float g_wkvT[D * 1024];

// ---------------- helpers ----------------
__device__ __forceinline__ void splitf(float v, u16& h, u16& l) {
    __nv_bfloat16 hb = __float2bfloat16(v);
    __nv_bfloat16 lb = __float2bfloat16(v - __bfloat162float(hb));
    h = __bfloat16_as_ushort(hb); l = __bfloat16_as_ushort(lb);
}
__device__ __forceinline__ u32 pckh(u16 a, u16 b) {
    u32 r; asm("mov.b32 %0,{%1,%2};" : "=r"(r) : "h"(a), "h"(b)); return r;
}
__device__ __forceinline__ u32 s2u(const void* p) {
    u32 a; asm("{ .reg .u64 t; cvta.to.shared.u64 t, %1; cvt.u32.u64 %0, t; }" : "=r"(a) : "l"(p));
    return a;
}
__device__ __forceinline__ void ldmA(u32* r, u32 a) {
    asm volatile("ldmatrix.sync.aligned.m8n8.x4.shared.b16 {%0,%1,%2,%3}, [%4];"
        : "=r"(r[0]), "=r"(r[1]), "=r"(r[2]), "=r"(r[3]) : "r"(a));
}
__device__ __forceinline__ void ldmB(u32* r, u32 a) {
    asm volatile("ldmatrix.sync.aligned.m8n8.x4.trans.shared.b16 {%0,%1,%2,%3}, [%4];"
        : "=r"(r[0]), "=r"(r[1]), "=r"(r[2]), "=r"(r[3]) : "r"(a));
}
__device__ __forceinline__ void mmabf(float* d, const u32* a, const u32* b) {
    asm volatile("mma.sync.aligned.m16n8k16.row.col.f32.bf16.bf16.f32 "
        "{%0,%1,%2,%3},{%4,%5,%6,%7},{%8,%9},{%0,%1,%2,%3};"
        : "+f"(d[0]), "+f"(d[1]), "+f"(d[2]), "+f"(d[3])
        : "r"(a[0]), "r"(a[1]), "r"(a[2]), "r"(a[3]), "r"(b[0]), "r"(b[1]));
}
__device__ __forceinline__ void stageB16(char* dst, const __nv_bfloat16* src, int rstride, int tid) {
    int r = tid >> 2, cb = (tid & 3) << 4;
    const uint4* s = (const uint4*)(src + (size_t)r * rstride + cb);
    uint4* d = (uint4*)(dst + (r * 72 + cb) * 2);
    d[0] = s[0]; d[1] = s[1];
}
__device__ __forceinline__ uint4 mkfrag(float b0a, float b0b, float b1a, float b1b) {
    u16 h0, l0, h1, l1; uint4 r;
    splitf(b0a, h0, l0); splitf(b0b, h1, l1); r.x = pckh(h0, h1); r.z = pckh(l0, l1);
    splitf(b1a, h0, l0); splitf(b1b, h1, l1); r.y = pckh(h0, h1); r.w = pckh(l0, l1);
    return r;
}
__device__ __forceinline__ float2 rec2(const char* smem, int lo_off, int off) {
    u32 hh = *(const u32*)(smem + off * 2);
    u32 ll = *(const u32*)(smem + lo_off + off * 2);
    float2 r;
    r.x = __bfloat162float(__ushort_as_bfloat16((u16)hh)) + __bfloat162float(__ushort_as_bfloat16((u16)ll));
    r.y = __bfloat162float(__ushort_as_bfloat16((u16)(hh >> 16))) + __bfloat162float(__ushort_as_bfloat16((u16)(ll >> 16)));
    return r;
}

// ---------------- launch 1: weight prep (grid 832 x 256) ----------------
__global__ void prep_kernel(const float* __restrict__ wq,
                            const float* __restrict__ wkv,
                            const float* __restrict__ wout,
                            const float* __restrict__ cw) {
    int bid = blockIdx.x, t = threadIdx.x;
    if (bid < 128) {                       // woF: 32768 entries
        int e = bid * 256 + t;
        int ks = e >> 10, n8 = (e >> 5) & 31, lane = e & 31;
        int k0 = ks * 16 + (lane & 3) * 2, c = n8 * 8 + (lane >> 2);
        const float* w = wout + (size_t)c * 512;
        g_woF[e] = mkfrag(w[k0], w[k0 + 1], w[k0 + 8], w[k0 + 9]);
    } else if (bid < 320) {                // cwF: 49152 entries
        int e = (bid - 128) * 256 + t;
        int ks = e >> 10, n8 = (e >> 5) & 31, lane = e & 31;
        int k0 = ks * 16 + (lane & 3) * 2, c = n8 * 8 + (lane >> 2);
        const float* w = cw + (size_t)c * 768;
        float b[4];
        #pragma unroll
        for (int q = 0; q < 4; q++) {
            int k = k0 + ((q & 1) ? 1 : 0) + ((q >> 1) ? 8 : 0);
            b[q] = w[(k & 255) * 3 + (k >> 8)];
        }
        g_cwF[e] = mkfrag(b[0], b[1], b[2], b[3]);
    } else if (bid < 576) {                // wkvT: k = 0..255
        int k = bid - 320;
        #pragma unroll
        for (int u = 0; u < 4; u++)
            g_wkvT[k * 1024 + t + u * 256] = wkv[(size_t)(t + u * 256) * 256 + k];
    } else {                               // wq split: k = 0..255
        int k = bid - 576;
        u16 h0, l0;
        splitf(wq[t * 256 + k], h0, l0);
        g_wqTH[k * 512 + t] = __ushort_as_bfloat16(h0);
        g_wqTL[k * 512 + t] = __ushort_as_bfloat16(l0);
        splitf(wq[(t + 256) * 256 + k], h0, l0);
        g_wqTH[k * 512 + t + 256] = __ushort_as_bfloat16(h0);
        g_wqTL[k * 512 + t + 256] = __ushort_as_bfloat16(l0);
    }
}

// ---------------- launch 2: pattern double-LN + kv projection ----------------
__device__ __forceinline__ float block_reduce_sum256(float v, float* scratch) {
    #pragma unroll
    for (int o = 16; o; o >>= 1) v += __shfl_xor_sync(0xffffffffu, v, o);
    int w = threadIdx.x >> 5;
    if ((threadIdx.x & 31) == 0) scratch[w] = v;
    __syncthreads();
    if (threadIdx.x < 32) {
        float s = (threadIdx.x < 8) ? scratch[threadIdx.x] : 0.f;
        #pragma unroll
        for (int o = 4; o; o >>= 1) s += __shfl_xor_sync(0xffffffffu, s, o);
        if (threadIdx.x == 0) scratch[0] = s;
    }
    __syncthreads();
    float r = scratch[0];
    __syncthreads();
    return r;
}

__global__ void kv_kernel(const float* __restrict__ pattern) {
    __shared__ float scr[8];
    __shared__ float pr[D];
    int p = blockIdx.x, t = threadIdx.x;
    float v = pattern[p * D + t];
    #pragma unroll
    for (int rep = 0; rep < 2; rep++) {
        float s  = block_reduce_sum256(v, scr);
        float s2 = block_reduce_sum256(v * v, scr);
        float mu = s * (1.f / D);
        v = (v - mu) * rsqrtf(s2 * (1.f / D) - mu * mu + 1e-5f);
    }
    pr[t] = v;
    __syncthreads();
    float acc[4] = {0.f, 0.f, 0.f, 0.f};
    for (int i = 0; i < D; i++) {
        float xv = pr[i];
        const float* wr = g_wkvT + i * 1024 + t;
        #pragma unroll
        for (int u = 0; u < 4; u++) acc[u] = fmaf(xv, wr[u * 256], acc[u]);
    }
    #pragma unroll
    for (int u = 0; u < 4; u++) {
        int j = t + u * 256;
        int h = j >> 7, r = j & 127;
        u16 hi, lo; splitf(acc[u], hi, lo);
        if (r < DA) {
            g_ktH[((size_t)(h * 64) + r) * 512 + p] = __ushort_as_bfloat16(hi);
            g_ktL[((size_t)(h * 64) + r) * 512 + p] = __ushort_as_bfloat16(lo);
        } else {
            g_vH[((size_t)(h * 512) + p) * 64 + (r - DA)] = __ushort_as_bfloat16(hi);
            g_vL[((size_t)(h * 512) + p) * 64 + (r - DA)] = __ushort_as_bfloat16(lo);
        }
    }
}

// ---------------- launch 3: HMMA conv + residual + leaky + LN ----------------
// grid T/64, 256 thr. smem: XH@0 (66*264*2=34848), XL@34848, ss@69696 (128 f), sq@70208 (70720 B)
__global__ __launch_bounds__(256) void convln_kernel(const float* __restrict__ x,
                                                     const float* __restrict__ conv_b,
                                                     int L) {
    extern __shared__ char smem[];
    const int XLo = 34848;
    float* ss = (float*)(smem + 69696);
    float* sq = ss + 128;
    u32 sb = s2u(smem);
    int tid = threadIdx.x, lane = tid & 31, w = tid >> 5;
    int mt = w & 3, nh = w >> 2;
    int t0 = blockIdx.x * 64;
    int pos0 = t0 % L;
    int lrow = lane & 15, lcol = (lane >> 4) << 3;

    {   // stage X window rows 0..65 (row r = x[t0+r-2]) split hi/lo
        int c2 = tid & 127, rg = tid >> 7;
        for (int r = rg; r < 66; r += 2) {
            float2 v = make_float2(0.f, 0.f);
            if (pos0 + r >= 2) v = *(const float2*)&x[(size_t)(t0 + r - 2) * D + 2 * c2];
            u16 h0, l0, h1, l1; splitf(v.x, h0, l0); splitf(v.y, h1, l1);
            *(u32*)(smem + (r * 264 + 2 * c2) * 2)       = pckh(h0, h1);
            *(u32*)(smem + XLo + (r * 264 + 2 * c2) * 2) = pckh(l0, l1);
        }
    }
    __syncthreads();

    float acc[16][4];
    #pragma unroll
    for (int g = 0; g < 16; g++)
        #pragma unroll
        for (int q = 0; q < 4; q++) acc[g][q] = 0.f;

    for (int tap = 0; tap < 3; tap++) {
        for (int kk = 0; kk < 16; kk++) {
            int ks = tap * 16 + kk;
            u32 aH[4], aL[4];
            u32 ab = sb + ((mt * 16 + lrow + tap) * 264 + kk * 16 + lcol) * 2;
            ldmA(aH, ab); ldmA(aL, ab + XLo);
            const uint4* bf = g_cwF + ((size_t)ks * 32 + nh * 16) * 32 + lane;
            #pragma unroll
            for (int g = 0; g < 16; g++) {
                uint4 f = bf[g * 32];
                u32 bh[2] = {f.x, f.y}, bl[2] = {f.z, f.w};
                mmabf(acc[g], aH, bh); mmabf(acc[g], aL, bh); mmabf(acc[g], aH, bl);
            }
        }
    }

    // epilogue: bias + residual + leaky, per-token stats
    int ra = mt * 16 + (lane >> 2);
    float s_a = 0.f, q_a = 0.f, s_b = 0.f, q_b = 0.f;
    #pragma unroll
    for (int g = 0; g < 16; g++) {
        int c = nh * 128 + g * 8 + 2 * (lane & 3);
        float2 cb = *(const float2*)&conv_b[c];
        float2 xr0 = rec2(smem, XLo, (ra + 2) * 264 + c);
        float2 xr1 = rec2(smem, XLo, (ra + 10) * 264 + c);
        float v0 = acc[g][0] + cb.x + xr0.x, v1 = acc[g][1] + cb.y + xr0.y;
        float v2 = acc[g][2] + cb.x + xr1.x, v3 = acc[g][3] + cb.y + xr1.y;
        v0 = v0 > 0.f ? v0 : 0.01f * v0; v1 = v1 > 0.f ? v1 : 0.01f * v1;
        v2 = v2 > 0.f ? v2 : 0.01f * v2; v3 = v3 > 0.f ? v3 : 0.01f * v3;
        acc[g][0] = v0; acc[g][1] = v1; acc[g][2] = v2; acc[g][3] = v3;
        s_a += v0 + v1; q_a += v0 * v0 + v1 * v1;
        s_b += v2 + v3; q_b += v2 * v2 + v3 * v3;
    }
    s_a += __shfl_xor_sync(0xffffffffu, s_a, 1); s_a += __shfl_xor_sync(0xffffffffu, s_a, 2);
    q_a += __shfl_xor_sync(0xffffffffu, q_a, 1); q_a += __shfl_xor_sync(0xffffffffu, q_a, 2);
    s_b += __shfl_xor_sync(0xffffffffu, s_b, 1); s_b += __shfl_xor_sync(0xffffffffu, s_b, 2);
    q_b += __shfl_xor_sync(0xffffffffu, q_b, 1); q_b += __shfl_xor_sync(0xffffffffu, q_b, 2);
    if ((lane & 3) == 0) {
        ss[nh * 64 + ra] = s_a; sq[nh * 64 + ra] = q_a;
        ss[nh * 64 + ra + 8] = s_b; sq[nh * 64 + ra + 8] = q_b;
    }
    __syncthreads();
    float S0 = ss[ra] + ss[64 + ra], Q0 = sq[ra] + sq[64 + ra];
    float S1 = ss[ra + 8] + ss[64 + ra + 8], Q1 = sq[ra + 8] + sq[64 + ra + 8];
    float mu0 = S0 * (1.f / D), rs0 = rsqrtf(Q0 * (1.f / D) - mu0 * mu0 + 1e-5f);
    float mu1 = S1 * (1.f / D), rs1 = rsqrtf(Q1 * (1.f / D) - mu1 * mu1 + 1e-5f);
    #pragma unroll
    for (int g = 0; g < 16; g++) {
        int c = nh * 128 + g * 8 + 2 * (lane & 3);
        u16 h0, l0, h1, l1;
        splitf((acc[g][0] - mu0) * rs0, h0, l0); splitf((acc[g][1] - mu0) * rs0, h1, l1);
        *(u32*)&g_xnH[(size_t)(t0 + ra) * D + c] = pckh(h0, h1);
        *(u32*)&g_xnL[(size_t)(t0 + ra) * D + c] = pckh(l0, l1);
        splitf((acc[g][2] - mu1) * rs1, h0, l0); splitf((acc[g][3] - mu1) * rs1, h1, l1);
        *(u32*)&g_xnH[(size_t)(t0 + ra + 8) * D + c] = pckh(h0, h1);
        *(u32*)&g_xnL[(size_t)(t0 + ra + 8) * D + c] = pckh(l0, l1);
    }
}

// ---------------- launch 4 (PROFILED): HMMA fused qproj + attention ----------------
// grid (T/64, 8), 256 threads. smem 74240 B
__global__ __launch_bounds__(256) void attn_kernel() {
    extern __shared__ char smem[];
    const int QHo = 0, QLo = 9216, AHo = 18432, ALo = 27648, BHo = 36864, BLo = 46080,
              VHo = 55296, VLo = 64512;
    u32 sb = s2u(smem);
    int tid = threadIdx.x, lane = tid & 31, w = tid >> 5;
    int mt = w & 3, nh = w >> 2;
    int t0 = blockIdx.x * 64, h = blockIdx.y;
    float* spart = (float*)(smem + 73728);
    int lrow = lane & 15, lcol = (lane >> 4) << 3;

    float qD[4][4];
    #pragma unroll
    for (int i = 0; i < 4; i++)
        #pragma unroll
        for (int j = 0; j < 4; j++) qD[i][j] = 0.f;
    for (int c = 0; c < 4; c++) {
        __syncthreads();
        stageB16(smem + AHo, g_xnH + (size_t)t0 * D + c * 64, D, tid);
        stageB16(smem + ALo, g_xnL + (size_t)t0 * D + c * 64, D, tid);
        stageB16(smem + BHo, g_wqTH + (size_t)(c * 64) * 512 + h * 64, 512, tid);
        stageB16(smem + BLo, g_wqTL + (size_t)(c * 64) * 512 + h * 64, 512, tid);
        __syncthreads();
        #pragma unroll
        for (int ks = 0; ks < 4; ks++) {
            int kb = ks * 16;
            u32 aH[4], aL[4];
            ldmA(aH, sb + AHo + ((mt * 16 + lrow) * 72 + kb + lcol) * 2);
            ldmA(aL, sb + ALo + ((mt * 16 + lrow) * 72 + kb + lcol) * 2);
            #pragma unroll
            for (int ng = 0; ng < 2; ng++) {
                int nb = nh * 32 + ng * 16;
                u32 bH[4], bL[4];
                ldmB(bH, sb + BHo + ((kb + lrow) * 72 + nb + lcol) * 2);
                ldmB(bL, sb + BLo + ((kb + lrow) * 72 + nb + lcol) * 2);
                #pragma unroll
                for (int ti = 0; ti < 2; ti++) {
                    u32 bh2[2] = {bH[2 * ti], bH[2 * ti + 1]};
                    u32 bl2[2] = {bL[2 * ti], bL[2 * ti + 1]};
                    float* dd = qD[ng * 2 + ti];
                    mmabf(dd, aH, bh2); mmabf(dd, aL, bh2); mmabf(dd, aH, bl2);
                }
            }
        }
    }
    __syncthreads();
    {
        int r0 = mt * 16 + (lane >> 2);
        #pragma unroll
        for (int nt = 0; nt < 4; nt++) {
            int c0 = nh * 32 + nt * 8 + 2 * (lane & 3);
            u16 h0, l0, h1, l1;
            splitf(qD[nt][0], h0, l0); splitf(qD[nt][1], h1, l1);
            *(u32*)(smem + QHo + (r0 * 72 + c0) * 2) = pckh(h0, h1);
            *(u32*)(smem + QLo + (r0 * 72 + c0) * 2) = pckh(l0, l1);
            splitf(qD[nt][2], h0, l0); splitf(qD[nt][3], h1, l1);
            *(u32*)(smem + QHo + ((r0 + 8) * 72 + c0) * 2) = pckh(h0, h1);
            *(u32*)(smem + QLo + ((r0 + 8) * 72 + c0) * 2) = pckh(l0, l1);
        }
    }

    float pvD[4][4];
    #pragma unroll
    for (int i = 0; i < 4; i++)
        #pragma unroll
        for (int j = 0; j < 4; j++) pvD[i][j] = 0.f;
    float rs0 = 0.f, rs1 = 0.f;
    for (int b = 0; b < 8; b++) {
        __syncthreads();
        stageB16(smem + BHo, g_ktH + (size_t)(h * 64) * 512 + b * 64, 512, tid);
        stageB16(smem + BLo, g_ktL + (size_t)(h * 64) * 512 + b * 64, 512, tid);
        stageB16(smem + VHo, g_vH + ((size_t)(h * 512) + b * 64) * 64, 64, tid);
        stageB16(smem + VLo, g_vL + ((size_t)(h * 512) + b * 64) * 64, 64, tid);
        __syncthreads();
        float sD[4][4];
        #pragma unroll
        for (int i = 0; i < 4; i++)
            #pragma unroll
            for (int j = 0; j < 4; j++) sD[i][j] = 0.f;
        #pragma unroll
        for (int ks = 0; ks < 4; ks++) {
            int kb = ks * 16;
            u32 aH[4], aL[4];
            ldmA(aH, sb + QHo + ((mt * 16 + lrow) * 72 + kb + lcol) * 2);
            ldmA(aL, sb + QLo + ((mt * 16 + lrow) * 72 + kb + lcol) * 2);
            #pragma unroll
            for (int ng = 0; ng < 2; ng++) {
                int nb = nh * 32 + ng * 16;
                u32 bH[4], bL[4];
                ldmB(bH, sb + BHo + ((kb + lrow) * 72 + nb + lcol) * 2);
                ldmB(bL, sb + BLo + ((kb + lrow) * 72 + nb + lcol) * 2);
                #pragma unroll
                for (int ti = 0; ti < 2; ti++) {
                    u32 bh2[2] = {bH[2 * ti], bH[2 * ti + 1]};
                    u32 bl2[2] = {bL[2 * ti], bL[2 * ti + 1]};
                    float* dd = sD[ng * 2 + ti];
                    mmabf(dd, aH, bh2); mmabf(dd, aL, bh2); mmabf(dd, aH, bl2);
                }
            }
        }
        {
            int r0 = mt * 16 + (lane >> 2);
            #pragma unroll
            for (int nt = 0; nt < 4; nt++) {
                int c0 = nh * 32 + nt * 8 + 2 * (lane & 3);
                float e0 = __expf(0.125f * sD[nt][0]), e1 = __expf(0.125f * sD[nt][1]);
                float e2 = __expf(0.125f * sD[nt][2]), e3 = __expf(0.125f * sD[nt][3]);
                rs0 += e0 + e1; rs1 += e2 + e3;
                u16 h0, l0, h1, l1;
                splitf(e0, h0, l0); splitf(e1, h1, l1);
                *(u32*)(smem + AHo + (r0 * 72 + c0) * 2) = pckh(h0, h1);
                *(u32*)(smem + ALo + (r0 * 72 + c0) * 2) = pckh(l0, l1);
                splitf(e2, h0, l0); splitf(e3, h1, l1);
                *(u32*)(smem + AHo + ((r0 + 8) * 72 + c0) * 2) = pckh(h0, h1);
                *(u32*)(smem + ALo + ((r0 + 8) * 72 + c0) * 2) = pckh(l0, l1);
            }
        }
        __syncthreads();
        #pragma unroll
        for (int ks = 0; ks < 4; ks++) {
            int kb = ks * 16;
            u32 aH[4], aL[4];
            ldmA(aH, sb + AHo + ((mt * 16 + lrow) * 72 + kb + lcol) * 2);
            ldmA(aL, sb + ALo + ((mt * 16 + lrow) * 72 + kb + lcol) * 2);
            #pragma unroll
            for (int ng = 0; ng < 2; ng++) {
                int nb = nh * 32 + ng * 16;
                u32 bH[4], bL[4];
                ldmB(bH, sb + VHo + ((kb + lrow) * 72 + nb + lcol) * 2);
                ldmB(bL, sb + VLo + ((kb + lrow) * 72 + nb + lcol) * 2);
                #pragma unroll
                for (int ti = 0; ti < 2; ti++) {
                    u32 bh2[2] = {bH[2 * ti], bH[2 * ti + 1]};
                    u32 bl2[2] = {bL[2 * ti], bL[2 * ti + 1]};
                    float* dd = pvD[ng * 2 + ti];
                    mmabf(dd, aH, bh2); mmabf(dd, aL, bh2); mmabf(dd, aH, bl2);
                }
            }
        }
    }
    rs0 += __shfl_xor_sync(0xffffffffu, rs0, 1);
    rs0 += __shfl_xor_sync(0xffffffffu, rs0, 2);
    rs1 += __shfl_xor_sync(0xffffffffu, rs1, 1);
    rs1 += __shfl_xor_sync(0xffffffffu, rs1, 2);
    if ((lane & 3) == 0) {
        spart[nh * 64 + mt * 16 + (lane >> 2)]     = rs0;
        spart[nh * 64 + mt * 16 + 8 + (lane >> 2)] = rs1;
    }
    __syncthreads();
    {
        int r0 = mt * 16 + (lane >> 2);
        float ri0 = 1.f / (spart[r0] + spart[64 + r0]);
        float ri1 = 1.f / (spart[r0 + 8] + spart[64 + r0 + 8]);
        #pragma unroll
        for (int nt = 0; nt < 4; nt++) {
            int c0 = nh * 32 + nt * 8 + 2 * (lane & 3);
            u16 h0, l0, h1, l1;
            splitf(pvD[nt][0] * ri0, h0, l0); splitf(pvD[nt][1] * ri0, h1, l1);
            *(u32*)&g_attH[(size_t)(t0 + r0) * 512 + h * 64 + c0] = pckh(h0, h1);
            *(u32*)&g_attL[(size_t)(t0 + r0) * 512 + h * 64 + c0] = pckh(l0, l1);
            splitf(pvD[nt][2] * ri1, h0, l0); splitf(pvD[nt][3] * ri1, h1, l1);
            *(u32*)&g_attH[(size_t)(t0 + r0 + 8) * 512 + h * 64 + c0] = pckh(h0, h1);
            *(u32*)&g_attL[(size_t)(t0 + r0 + 8) * 512 + h * 64 + c0] = pckh(l0, l1);
        }
    }
}

// ---------------- launch 5: HMMA out projection + final LN ----------------
// grid T/64, 256 thr. smem: AH@0 (9216), AL@9216, ss@18432 (128f), sq@18944 (19456 B)
__global__ __launch_bounds__(256) void outln_kernel(const float* __restrict__ bout,
                                                    float* __restrict__ out) {
    extern __shared__ char smem[];
    const int ALo = 9216;
    float* ss = (float*)(smem + 18432);
    float* sq = ss + 128;
    u32 sb = s2u(smem);
    int tid = threadIdx.x, lane = tid & 31, w = tid >> 5;
    int mt = w & 3, nh = w >> 2;
    int t0 = blockIdx.x * 64;
    int lrow = lane & 15, lcol = (lane >> 4) << 3;

    float acc[16][4];
    #pragma unroll
    for (int g = 0; g < 16; g++)
        #pragma unroll
        for (int q = 0; q < 4; q++) acc[g][q] = 0.f;

    for (int c8 = 0; c8 < 8; c8++) {
        __syncthreads();
        stageB16(smem, g_attH + (size_t)t0 * 512 + c8 * 64, 512, tid);
        stageB16(smem + ALo, g_attL + (size_t)t0 * 512 + c8 * 64, 512, tid);
        __syncthreads();
        #pragma unroll
        for (int kk = 0; kk < 4; kk++) {
            int ks = c8 * 4 + kk;
            u32 aH[4], aL[4];
            u32 ab = sb + ((mt * 16 + lrow) * 72 + kk * 16 + lcol) * 2;
            ldmA(aH, ab); ldmA(aL, ab + ALo);
            const uint4* bf = g_woF + ((size_t)ks * 32 + nh * 16) * 32 + lane;
            #pragma unroll
            for (int g = 0; g < 16; g++) {
                uint4 f = bf[g * 32];
                u32 bh[2] = {f.x, f.y}, bl[2] = {f.z, f.w};
                mmabf(acc[g], aH, bh); mmabf(acc[g], aL, bh); mmabf(acc[g], aH, bl);
            }
        }
    }

    int ra = mt * 16 + (lane >> 2);
    float s_a = 0.f, q_a = 0.f, s_b = 0.f, q_b = 0.f;
    #pragma unroll
    for (int g = 0; g < 16; g++) {
        int c = nh * 128 + g * 8 + 2 * (lane & 3);
        float2 cb = *(const float2*)&bout[c];
        float v0 = acc[g][0] + cb.x, v1 = acc[g][1] + cb.y;
        float v2 = acc[g][2] + cb.x, v3 = acc[g][3] + cb.y;
        acc[g][0] = v0; acc[g][1] = v1; acc[g][2] = v2; acc[g][3] = v3;
        s_a += v0 + v1; q_a += v0 * v0 + v1 * v1;
        s_b += v2 + v3; q_b += v2 * v2 + v3 * v3;
    }
    s_a += __shfl_xor_sync(0xffffffffu, s_a, 1); s_a += __shfl_xor_sync(0xffffffffu, s_a, 2);
    q_a += __shfl_xor_sync(0xffffffffu, q_a, 1); q_a += __shfl_xor_sync(0xffffffffu, q_a, 2);
    s_b += __shfl_xor_sync(0xffffffffu, s_b, 1); s_b += __shfl_xor_sync(0xffffffffu, s_b, 2);
    q_b += __shfl_xor_sync(0xffffffffu, q_b, 1); q_b += __shfl_xor_sync(0xffffffffu, q_b, 2);
    if ((lane & 3) == 0) {
        ss[nh * 64 + ra] = s_a; sq[nh * 64 + ra] = q_a;
        ss[nh * 64 + ra + 8] = s_b; sq[nh * 64 + ra + 8] = q_b;
    }
    __syncthreads();
    float S0 = ss[ra] + ss[64 + ra], Q0 = sq[ra] + sq[64 + ra];
    float S1 = ss[ra + 8] + ss[64 + ra + 8], Q1 = sq[ra + 8] + sq[64 + ra + 8];
    float mu0 = S0 * (1.f / D), r0 = rsqrtf(Q0 * (1.f / D) - mu0 * mu0 + 1e-5f);
    float mu1 = S1 * (1.f / D), r1 = rsqrtf(Q1 * (1.f / D) - mu1 * mu1 + 1e-5f);
    #pragma unroll
    for (int g = 0; g < 16; g++) {
        int c = nh * 128 + g * 8 + 2 * (lane & 3);
        *(float2*)&out[(size_t)(t0 + ra) * D + c] =
            make_float2((acc[g][0] - mu0) * r0, (acc[g][1] - mu0) * r0);
        *(float2*)&out[(size_t)(t0 + ra + 8) * D + c] =
            make_float2((acc[g][2] - mu1) * r1, (acc[g][3] - mu1) * r1);
    }
}

// ---------------- launch ----------------
extern "C" void kernel_launch(void* const* d_in, const int* in_sizes, int n_in,
                              void* d_out, int out_size) {
    const float* x       = (const float*)d_in[0];
    const float* conv_w  = (const float*)d_in[1];
    const float* conv_b  = (const float*)d_in[2];
    const float* pattern = (const float*)d_in[3];
    const float* wq      = (const float*)d_in[4];
    const float* wkv     = (const float*)d_in[5];
    const float* wout    = (const float*)d_in[6];
    const float* bout    = (const float*)d_in[7];

    int T = in_sizes[0] / D;
    int B = in_sizes[8] - 1;
    int L = T / B;

    int convln_smem = 70720;
    int attn_smem   = 74240;
    int outln_smem  = 19456;
    cudaFuncSetAttribute(convln_kernel, cudaFuncAttributeMaxDynamicSharedMemorySize, convln_smem);
    cudaFuncSetAttribute(attn_kernel,   cudaFuncAttributeMaxDynamicSharedMemorySize, attn_smem);
    cudaFuncSetAttribute(outln_kernel,  cudaFuncAttributeMaxDynamicSharedMemorySize, outln_smem);

    prep_kernel <<<832, 256>>>(wq, wkv, wout, conv_w);         // 1
    kv_kernel   <<<PP, 256>>>(pattern);                        // 2
    convln_kernel<<<T / 64, 256, convln_smem>>>(x, conv_b, L); // 3
    dim3 ag(T / 64, HH);
    attn_kernel <<<ag, 256, attn_smem>>>();                    // 4 (profiled)
    outln_kernel<<<T / 64, 256, outln_smem>>>(bout, (float*)d_out); // 5
}

// round 16
// speedup vs baseline: 2.2662x; 1.0111x over previous
#include <cuda_runtime.h>
#include <cuda_bf16.h>

#define D    256
#define PP   512
#define HH   8
#define DA   64
#define TMAX 65536
typedef unsigned long long u64;
typedef unsigned int u32;
typedef unsigned short u16;

// ---------------- device scratch ----------------
__device__ __align__(16) __nv_bfloat16 g_ktH[HH * DA * PP];   // [h][d][p]
__device__ __align__(16) __nv_bfloat16 g_ktL[HH * DA * PP];
__device__ __align__(16) __nv_bfloat16 g_vH [HH * PP * DA];   // [h][p][d]
__device__ __align__(16) __nv_bfloat16 g_vL [HH * PP * DA];
__device__ __align__(16) __nv_bfloat16 g_xnH[(size_t)TMAX * D];
__device__ __align__(16) __nv_bfloat16 g_xnL[(size_t)TMAX * D];
__device__ __align__(16) __nv_bfloat16 g_attH[(size_t)TMAX * 512];
__device__ __align__(16) __nv_bfloat16 g_attL[(size_t)TMAX * 512];
__device__ __align__(16) __nv_bfloat16 g_wqTH[256 * 512];     // [k][j]
__device__ __align__(16) __nv_bfloat16 g_wqTL[256 * 512];
__device__ uint4 g_cwF[48 * 32 * 32];
__device__ uint4 g_woF[32 * 32 * 32];
__device__ float g_wkvT[D * 1024];

// ---------------- helpers ----------------
__device__ __forceinline__ void splitf(float v, u16& h, u16& l) {
    __nv_bfloat16 hb = __float2bfloat16(v);
    __nv_bfloat16 lb = __float2bfloat16(v - __bfloat162float(hb));
    h = __bfloat16_as_ushort(hb); l = __bfloat16_as_ushort(lb);
}
__device__ __forceinline__ u32 pckh(u16 a, u16 b) {
    u32 r; asm("mov.b32 %0,{%1,%2};" : "=r"(r) : "h"(a), "h"(b)); return r;
}
__device__ __forceinline__ u32 s2u(const void* p) {
    u32 a; asm("{ .reg .u64 t; cvta.to.shared.u64 t, %1; cvt.u32.u64 %0, t; }" : "=r"(a) : "l"(p));
    return a;
}
__device__ __forceinline__ void ldmA(u32* r, u32 a) {
    asm volatile("ldmatrix.sync.aligned.m8n8.x4.shared.b16 {%0,%1,%2,%3}, [%4];"
        : "=r"(r[0]), "=r"(r[1]), "=r"(r[2]), "=r"(r[3]) : "r"(a));
}
__device__ __forceinline__ void ldmB(u32* r, u32 a) {
    asm volatile("ldmatrix.sync.aligned.m8n8.x4.trans.shared.b16 {%0,%1,%2,%3}, [%4];"
        : "=r"(r[0]), "=r"(r[1]), "=r"(r[2]), "=r"(r[3]) : "r"(a));
}
__device__ __forceinline__ void mmabf(float* d, const u32* a, const u32* b) {
    asm volatile("mma.sync.aligned.m16n8k16.row.col.f32.bf16.bf16.f32 "
        "{%0,%1,%2,%3},{%4,%5,%6,%7},{%8,%9},{%0,%1,%2,%3};"
        : "+f"(d[0]), "+f"(d[1]), "+f"(d[2]), "+f"(d[3])
        : "r"(a[0]), "r"(a[1]), "r"(a[2]), "r"(a[3]), "r"(b[0]), "r"(b[1]));
}
__device__ __forceinline__ void stageB16(char* dst, const __nv_bfloat16* src, int rstride, int tid) {
    int r = tid >> 2, cb = (tid & 3) << 4;
    const uint4* s = (const uint4*)(src + (size_t)r * rstride + cb);
    uint4* d = (uint4*)(dst + (r * 72 + cb) * 2);
    d[0] = s[0]; d[1] = s[1];
}
__device__ __forceinline__ uint4 mkfrag(float b0a, float b0b, float b1a, float b1b) {
    u16 h0, l0, h1, l1; uint4 r;
    splitf(b0a, h0, l0); splitf(b0b, h1, l1); r.x = pckh(h0, h1); r.z = pckh(l0, l1);
    splitf(b1a, h0, l0); splitf(b1b, h1, l1); r.y = pckh(h0, h1); r.w = pckh(l0, l1);
    return r;
}
__device__ __forceinline__ float2 rec2(const char* smem, int lo_off, int off) {
    u32 hh = *(const u32*)(smem + off * 2);
    u32 ll = *(const u32*)(smem + lo_off + off * 2);
    float2 r;
    r.x = __bfloat162float(__ushort_as_bfloat16((u16)hh)) + __bfloat162float(__ushort_as_bfloat16((u16)ll));
    r.y = __bfloat162float(__ushort_as_bfloat16((u16)(hh >> 16))) + __bfloat162float(__ushort_as_bfloat16((u16)(ll >> 16)));
    return r;
}

// ---------------- launch 1: weight prep (grid 832 x 256) ----------------
__global__ void prep_kernel(const float* __restrict__ wq,
                            const float* __restrict__ wkv,
                            const float* __restrict__ wout,
                            const float* __restrict__ cw) {
    int bid = blockIdx.x, t = threadIdx.x;
    if (bid < 128) {
        int e = bid * 256 + t;
        int ks = e >> 10, n8 = (e >> 5) & 31, lane = e & 31;
        int k0 = ks * 16 + (lane & 3) * 2, c = n8 * 8 + (lane >> 2);
        const float* w = wout + (size_t)c * 512;
        g_woF[e] = mkfrag(w[k0], w[k0 + 1], w[k0 + 8], w[k0 + 9]);
    } else if (bid < 320) {
        int e = (bid - 128) * 256 + t;
        int ks = e >> 10, n8 = (e >> 5) & 31, lane = e & 31;
        int k0 = ks * 16 + (lane & 3) * 2, c = n8 * 8 + (lane >> 2);
        const float* w = cw + (size_t)c * 768;
        float b[4];
        #pragma unroll
        for (int q = 0; q < 4; q++) {
            int k = k0 + ((q & 1) ? 1 : 0) + ((q >> 1) ? 8 : 0);
            b[q] = w[(k & 255) * 3 + (k >> 8)];
        }
        g_cwF[e] = mkfrag(b[0], b[1], b[2], b[3]);
    } else if (bid < 576) {
        int k = bid - 320;
        #pragma unroll
        for (int u = 0; u < 4; u++)
            g_wkvT[k * 1024 + t + u * 256] = wkv[(size_t)(t + u * 256) * 256 + k];
    } else {
        int k = bid - 576;
        u16 h0, l0;
        splitf(wq[t * 256 + k], h0, l0);
        g_wqTH[k * 512 + t] = __ushort_as_bfloat16(h0);
        g_wqTL[k * 512 + t] = __ushort_as_bfloat16(l0);
        splitf(wq[(t + 256) * 256 + k], h0, l0);
        g_wqTH[k * 512 + t + 256] = __ushort_as_bfloat16(h0);
        g_wqTL[k * 512 + t + 256] = __ushort_as_bfloat16(l0);
    }
}

// ---------------- launch 2: pattern double-LN + kv projection ----------------
__device__ __forceinline__ float block_reduce_sum256(float v, float* scratch) {
    #pragma unroll
    for (int o = 16; o; o >>= 1) v += __shfl_xor_sync(0xffffffffu, v, o);
    int w = threadIdx.x >> 5;
    if ((threadIdx.x & 31) == 0) scratch[w] = v;
    __syncthreads();
    if (threadIdx.x < 32) {
        float s = (threadIdx.x < 8) ? scratch[threadIdx.x] : 0.f;
        #pragma unroll
        for (int o = 4; o; o >>= 1) s += __shfl_xor_sync(0xffffffffu, s, o);
        if (threadIdx.x == 0) scratch[0] = s;
    }
    __syncthreads();
    float r = scratch[0];
    __syncthreads();
    return r;
}

__global__ void kv_kernel(const float* __restrict__ pattern) {
    __shared__ float scr[8];
    __shared__ float pr[D];
    int p = blockIdx.x, t = threadIdx.x;
    float v = pattern[p * D + t];
    #pragma unroll
    for (int rep = 0; rep < 2; rep++) {
        float s  = block_reduce_sum256(v, scr);
        float s2 = block_reduce_sum256(v * v, scr);
        float mu = s * (1.f / D);
        v = (v - mu) * rsqrtf(s2 * (1.f / D) - mu * mu + 1e-5f);
    }
    pr[t] = v;
    __syncthreads();
    float acc[4] = {0.f, 0.f, 0.f, 0.f};
    for (int i = 0; i < D; i++) {
        float xv = pr[i];
        const float* wr = g_wkvT + i * 1024 + t;
        #pragma unroll
        for (int u = 0; u < 4; u++) acc[u] = fmaf(xv, wr[u * 256], acc[u]);
    }
    #pragma unroll
    for (int u = 0; u < 4; u++) {
        int j = t + u * 256;
        int h = j >> 7, r = j & 127;
        u16 hi, lo; splitf(acc[u], hi, lo);
        if (r < DA) {
            g_ktH[((size_t)(h * 64) + r) * 512 + p] = __ushort_as_bfloat16(hi);
            g_ktL[((size_t)(h * 64) + r) * 512 + p] = __ushort_as_bfloat16(lo);
        } else {
            g_vH[((size_t)(h * 512) + p) * 64 + (r - DA)] = __ushort_as_bfloat16(hi);
            g_vL[((size_t)(h * 512) + p) * 64 + (r - DA)] = __ushort_as_bfloat16(lo);
        }
    }
}

// ---------------- launch 3: HMMA conv + residual + leaky + LN ----------------
__global__ __launch_bounds__(256) void convln_kernel(const float* __restrict__ x,
                                                     const float* __restrict__ conv_b,
                                                     int L) {
    extern __shared__ char smem[];
    const int XLo = 34848;
    float* ss = (float*)(smem + 69696);
    float* sq = ss + 128;
    u32 sb = s2u(smem);
    int tid = threadIdx.x, lane = tid & 31, w = tid >> 5;
    int mt = w & 3, nh = w >> 2;
    int t0 = blockIdx.x * 64;
    int pos0 = t0 % L;
    int lrow = lane & 15, lcol = (lane >> 4) << 3;

    {
        int c2 = tid & 127, rg = tid >> 7;
        for (int r = rg; r < 66; r += 2) {
            float2 v = make_float2(0.f, 0.f);
            if (pos0 + r >= 2) v = *(const float2*)&x[(size_t)(t0 + r - 2) * D + 2 * c2];
            u16 h0, l0, h1, l1; splitf(v.x, h0, l0); splitf(v.y, h1, l1);
            *(u32*)(smem + (r * 264 + 2 * c2) * 2)       = pckh(h0, h1);
            *(u32*)(smem + XLo + (r * 264 + 2 * c2) * 2) = pckh(l0, l1);
        }
    }
    __syncthreads();

    float acc[16][4];
    #pragma unroll
    for (int g = 0; g < 16; g++)
        #pragma unroll
        for (int q = 0; q < 4; q++) acc[g][q] = 0.f;

    for (int tap = 0; tap < 3; tap++) {
        for (int kk = 0; kk < 16; kk++) {
            int ks = tap * 16 + kk;
            u32 aH[4], aL[4];
            u32 ab = sb + ((mt * 16 + lrow + tap) * 264 + kk * 16 + lcol) * 2;
            ldmA(aH, ab); ldmA(aL, ab + XLo);
            const uint4* bf = g_cwF + ((size_t)ks * 32 + nh * 16) * 32 + lane;
            #pragma unroll
            for (int g = 0; g < 16; g++) {
                uint4 f = bf[g * 32];
                u32 bh[2] = {f.x, f.y}, bl[2] = {f.z, f.w};
                mmabf(acc[g], aH, bh); mmabf(acc[g], aL, bh); mmabf(acc[g], aH, bl);
            }
        }
    }

    int ra = mt * 16 + (lane >> 2);
    float s_a = 0.f, q_a = 0.f, s_b = 0.f, q_b = 0.f;
    #pragma unroll
    for (int g = 0; g < 16; g++) {
        int c = nh * 128 + g * 8 + 2 * (lane & 3);
        float2 cb = *(const float2*)&conv_b[c];
        float2 xr0 = rec2(smem, XLo, (ra + 2) * 264 + c);
        float2 xr1 = rec2(smem, XLo, (ra + 10) * 264 + c);
        float v0 = acc[g][0] + cb.x + xr0.x, v1 = acc[g][1] + cb.y + xr0.y;
        float v2 = acc[g][2] + cb.x + xr1.x, v3 = acc[g][3] + cb.y + xr1.y;
        v0 = v0 > 0.f ? v0 : 0.01f * v0; v1 = v1 > 0.f ? v1 : 0.01f * v1;
        v2 = v2 > 0.f ? v2 : 0.01f * v2; v3 = v3 > 0.f ? v3 : 0.01f * v3;
        acc[g][0] = v0; acc[g][1] = v1; acc[g][2] = v2; acc[g][3] = v3;
        s_a += v0 + v1; q_a += v0 * v0 + v1 * v1;
        s_b += v2 + v3; q_b += v2 * v2 + v3 * v3;
    }
    s_a += __shfl_xor_sync(0xffffffffu, s_a, 1); s_a += __shfl_xor_sync(0xffffffffu, s_a, 2);
    q_a += __shfl_xor_sync(0xffffffffu, q_a, 1); q_a += __shfl_xor_sync(0xffffffffu, q_a, 2);
    s_b += __shfl_xor_sync(0xffffffffu, s_b, 1); s_b += __shfl_xor_sync(0xffffffffu, s_b, 2);
    q_b += __shfl_xor_sync(0xffffffffu, q_b, 1); q_b += __shfl_xor_sync(0xffffffffu, q_b, 2);
    if ((lane & 3) == 0) {
        ss[nh * 64 + ra] = s_a; sq[nh * 64 + ra] = q_a;
        ss[nh * 64 + ra + 8] = s_b; sq[nh * 64 + ra + 8] = q_b;
    }
    __syncthreads();
    float S0 = ss[ra] + ss[64 + ra], Q0 = sq[ra] + sq[64 + ra];
    float S1 = ss[ra + 8] + ss[64 + ra + 8], Q1 = sq[ra + 8] + sq[64 + ra + 8];
    float mu0 = S0 * (1.f / D), rs0 = rsqrtf(Q0 * (1.f / D) - mu0 * mu0 + 1e-5f);
    float mu1 = S1 * (1.f / D), rs1 = rsqrtf(Q1 * (1.f / D) - mu1 * mu1 + 1e-5f);
    #pragma unroll
    for (int g = 0; g < 16; g++) {
        int c = nh * 128 + g * 8 + 2 * (lane & 3);
        u16 h0, l0, h1, l1;
        splitf((acc[g][0] - mu0) * rs0, h0, l0); splitf((acc[g][1] - mu0) * rs0, h1, l1);
        *(u32*)&g_xnH[(size_t)(t0 + ra) * D + c] = pckh(h0, h1);
        *(u32*)&g_xnL[(size_t)(t0 + ra) * D + c] = pckh(l0, l1);
        splitf((acc[g][2] - mu1) * rs1, h0, l0); splitf((acc[g][3] - mu1) * rs1, h1, l1);
        *(u32*)&g_xnH[(size_t)(t0 + ra + 8) * D + c] = pckh(h0, h1);
        *(u32*)&g_xnL[(size_t)(t0 + ra + 8) * D + c] = pckh(l0, l1);
    }
}

// ---------------- launch 4 (PROFILED): HMMA attn, Q + P register-resident ----------------
// grid (T/64, 8), 256 threads. smem: QH@0 QL@9216 BH@18432 BL@27648 VH@36864 VL@46080
// part(reuse 18432..51200) spart@55296 -> total 55808 B
__global__ __launch_bounds__(256) void attn_kernel() {
    extern __shared__ char smem[];
    const int QHo = 0, QLo = 9216, BHo = 18432, BLo = 27648, VHo = 36864, VLo = 46080;
    u32 sb = s2u(smem);
    int tid = threadIdx.x, lane = tid & 31, w = tid >> 5;
    int mt = w & 3, nh = w >> 2;
    int t0 = blockIdx.x * 64, h = blockIdx.y;
    float* spart = (float*)(smem + 55296);
    int lrow = lane & 15, lcol = (lane >> 4) << 3;

    // ---- qproj: A = xn (VH/VL), B = wq (BH/BL) ----
    float qD[4][4];
    #pragma unroll
    for (int i = 0; i < 4; i++)
        #pragma unroll
        for (int j = 0; j < 4; j++) qD[i][j] = 0.f;
    for (int c = 0; c < 4; c++) {
        __syncthreads();
        stageB16(smem + VHo, g_xnH + (size_t)t0 * D + c * 64, D, tid);
        stageB16(smem + VLo, g_xnL + (size_t)t0 * D + c * 64, D, tid);
        stageB16(smem + BHo, g_wqTH + (size_t)(c * 64) * 512 + h * 64, 512, tid);
        stageB16(smem + BLo, g_wqTL + (size_t)(c * 64) * 512 + h * 64, 512, tid);
        __syncthreads();
        #pragma unroll
        for (int ks = 0; ks < 4; ks++) {
            int kb = ks * 16;
            u32 aH[4], aL[4];
            ldmA(aH, sb + VHo + ((mt * 16 + lrow) * 72 + kb + lcol) * 2);
            ldmA(aL, sb + VLo + ((mt * 16 + lrow) * 72 + kb + lcol) * 2);
            #pragma unroll
            for (int ng = 0; ng < 2; ng++) {
                int nb = nh * 32 + ng * 16;
                u32 bH[4], bL[4];
                ldmB(bH, sb + BHo + ((kb + lrow) * 72 + nb + lcol) * 2);
                ldmB(bL, sb + BLo + ((kb + lrow) * 72 + nb + lcol) * 2);
                #pragma unroll
                for (int ti = 0; ti < 2; ti++) {
                    u32 bh2[2] = {bH[2 * ti], bH[2 * ti + 1]};
                    u32 bl2[2] = {bL[2 * ti], bL[2 * ti + 1]};
                    float* dd = qD[ng * 2 + ti];
                    mmabf(dd, aH, bh2); mmabf(dd, aL, bh2); mmabf(dd, aH, bl2);
                }
            }
        }
    }
    __syncthreads();
    {   // store Q (split) into QH/QL
        int r0 = mt * 16 + (lane >> 2);
        #pragma unroll
        for (int nt = 0; nt < 4; nt++) {
            int c0 = nh * 32 + nt * 8 + 2 * (lane & 3);
            u16 h0, l0, h1, l1;
            splitf(qD[nt][0], h0, l0); splitf(qD[nt][1], h1, l1);
            *(u32*)(smem + QHo + (r0 * 72 + c0) * 2) = pckh(h0, h1);
            *(u32*)(smem + QLo + (r0 * 72 + c0) * 2) = pckh(l0, l1);
            splitf(qD[nt][2], h0, l0); splitf(qD[nt][3], h1, l1);
            *(u32*)(smem + QHo + ((r0 + 8) * 72 + c0) * 2) = pckh(h0, h1);
            *(u32*)(smem + QLo + ((r0 + 8) * 72 + c0) * 2) = pckh(l0, l1);
        }
    }
    __syncthreads();
    // ---- load Q fragments ONCE into registers (full k=64) ----
    u32 qaH[4][4], qaL[4][4];
    #pragma unroll
    for (int ks = 0; ks < 4; ks++) {
        ldmA(qaH[ks], sb + QHo + ((mt * 16 + lrow) * 72 + ks * 16 + lcol) * 2);
        ldmA(qaL[ks], sb + QLo + ((mt * 16 + lrow) * 72 + ks * 16 + lcol) * 2);
    }

    // ---- 8 batches: scores (reg-A) -> exp in regs -> PV partial (reg-A) ----
    float pvD[8][4];
    #pragma unroll
    for (int i = 0; i < 8; i++)
        #pragma unroll
        for (int j = 0; j < 4; j++) pvD[i][j] = 0.f;
    float rsum0 = 0.f, rsum1 = 0.f;
    for (int b = 0; b < 8; b++) {
        __syncthreads();
        stageB16(smem + BHo, g_ktH + (size_t)(h * 64) * 512 + b * 64, 512, tid);
        stageB16(smem + BLo, g_ktL + (size_t)(h * 64) * 512 + b * 64, 512, tid);
        stageB16(smem + VHo, g_vH + ((size_t)(h * 512) + b * 64) * 64, 64, tid);
        stageB16(smem + VLo, g_vL + ((size_t)(h * 512) + b * 64) * 64, 64, tid);
        __syncthreads();
        float sD[4][4];
        #pragma unroll
        for (int i = 0; i < 4; i++)
            #pragma unroll
            for (int j = 0; j < 4; j++) sD[i][j] = 0.f;
        #pragma unroll
        for (int ks = 0; ks < 4; ks++) {
            int kb = ks * 16;
            #pragma unroll
            for (int ng = 0; ng < 2; ng++) {
                int nb = nh * 32 + ng * 16;
                u32 bH[4], bL[4];
                ldmB(bH, sb + BHo + ((kb + lrow) * 72 + nb + lcol) * 2);
                ldmB(bL, sb + BLo + ((kb + lrow) * 72 + nb + lcol) * 2);
                #pragma unroll
                for (int ti = 0; ti < 2; ti++) {
                    u32 bh2[2] = {bH[2 * ti], bH[2 * ti + 1]};
                    u32 bl2[2] = {bL[2 * ti], bL[2 * ti + 1]};
                    float* dd = sD[ng * 2 + ti];
                    mmabf(dd, qaH[ks], bh2); mmabf(dd, qaL[ks], bh2); mmabf(dd, qaH[ks], bl2);
                }
            }
        }
        // exp in fragments + pack probs as A fragments (k = warp's 32 patterns)
        u32 paH[2][4], paL[2][4];
        #pragma unroll
        for (int g = 0; g < 2; g++) {
            float e[8];
            #pragma unroll
            for (int ti = 0; ti < 2; ti++)
                #pragma unroll
                for (int q = 0; q < 4; q++)
                    e[ti * 4 + q] = __expf(0.125f * sD[g * 2 + ti][q]);
            rsum0 += e[0] + e[1] + e[4] + e[5];
            rsum1 += e[2] + e[3] + e[6] + e[7];
            u16 h0, l0, h1, l1;
            splitf(e[0], h0, l0); splitf(e[1], h1, l1);
            paH[g][0] = pckh(h0, h1); paL[g][0] = pckh(l0, l1);
            splitf(e[2], h0, l0); splitf(e[3], h1, l1);
            paH[g][1] = pckh(h0, h1); paL[g][1] = pckh(l0, l1);
            splitf(e[4], h0, l0); splitf(e[5], h1, l1);
            paH[g][2] = pckh(h0, h1); paL[g][2] = pckh(l0, l1);
            splitf(e[6], h0, l0); splitf(e[7], h1, l1);
            paH[g][3] = pckh(h0, h1); paL[g][3] = pckh(l0, l1);
        }
        // PV partial: k rows = nh*32 + g*16 within this batch's V tile
        #pragma unroll
        for (int g = 0; g < 2; g++) {
            int krow = nh * 32 + g * 16;
            #pragma unroll
            for (int ng = 0; ng < 4; ng++) {
                int nb = ng * 16;
                u32 vH[4], vL[4];
                ldmB(vH, sb + VHo + ((krow + lrow) * 72 + nb + lcol) * 2);
                ldmB(vL, sb + VLo + ((krow + lrow) * 72 + nb + lcol) * 2);
                #pragma unroll
                for (int ti = 0; ti < 2; ti++) {
                    u32 vh2[2] = {vH[2 * ti], vH[2 * ti + 1]};
                    u32 vl2[2] = {vL[2 * ti], vL[2 * ti + 1]};
                    float* dd = pvD[ng * 2 + ti];
                    mmabf(dd, paH[g], vh2); mmabf(dd, paL[g], vh2); mmabf(dd, paH[g], vl2);
                }
            }
        }
    }
    // ---- reduce across nh halves via smem ----
    rsum0 += __shfl_xor_sync(0xffffffffu, rsum0, 1);
    rsum0 += __shfl_xor_sync(0xffffffffu, rsum0, 2);
    rsum1 += __shfl_xor_sync(0xffffffffu, rsum1, 1);
    rsum1 += __shfl_xor_sync(0xffffffffu, rsum1, 2);
    __syncthreads();                 // B/V reads done; reuse region as part buffer
    float* part = (float*)(smem + BHo);   // [2][64][64]
    {
        int r = mt * 16 + (lane >> 2);
        if ((lane & 3) == 0) {
            spart[nh * 64 + r] = rsum0;
            spart[nh * 64 + r + 8] = rsum1;
        }
        #pragma unroll
        for (int nt = 0; nt < 8; nt++) {
            int c = (nt >> 1) * 16 + (nt & 1) * 8 + 2 * (lane & 3);
            part[(nh * 64 + r) * 64 + c]     = pvD[nt][0];
            part[(nh * 64 + r) * 64 + c + 1] = pvD[nt][1];
            part[(nh * 64 + r + 8) * 64 + c]     = pvD[nt][2];
            part[(nh * 64 + r + 8) * 64 + c + 1] = pvD[nt][3];
        }
    }
    __syncthreads();
    {   // combine halves, normalize, split-store
        int row = tid >> 2, cb = (tid & 3) * 16;
        float rinv = 1.f / (spart[row] + spart[64 + row]);
        #pragma unroll
        for (int i = 0; i < 16; i += 2) {
            float v0 = (part[row * 64 + cb + i]     + part[(64 + row) * 64 + cb + i])     * rinv;
            float v1 = (part[row * 64 + cb + i + 1] + part[(64 + row) * 64 + cb + i + 1]) * rinv;
            u16 h0, l0, h1, l1;
            splitf(v0, h0, l0); splitf(v1, h1, l1);
            *(u32*)&g_attH[(size_t)(t0 + row) * 512 + h * 64 + cb + i] = pckh(h0, h1);
            *(u32*)&g_attL[(size_t)(t0 + row) * 512 + h * 64 + cb + i] = pckh(l0, l1);
        }
    }
}

// ---------------- launch 5: HMMA out projection + final LN ----------------
__global__ __launch_bounds__(256) void outln_kernel(const float* __restrict__ bout,
                                                    float* __restrict__ out) {
    extern __shared__ char smem[];
    const int ALo = 9216;
    float* ss = (float*)(smem + 18432);
    float* sq = ss + 128;
    u32 sb = s2u(smem);
    int tid = threadIdx.x, lane = tid & 31, w = tid >> 5;
    int mt = w & 3, nh = w >> 2;
    int t0 = blockIdx.x * 64;
    int lrow = lane & 15, lcol = (lane >> 4) << 3;

    float acc[16][4];
    #pragma unroll
    for (int g = 0; g < 16; g++)
        #pragma unroll
        for (int q = 0; q < 4; q++) acc[g][q] = 0.f;

    for (int c8 = 0; c8 < 8; c8++) {
        __syncthreads();
        stageB16(smem, g_attH + (size_t)t0 * 512 + c8 * 64, 512, tid);
        stageB16(smem + ALo, g_attL + (size_t)t0 * 512 + c8 * 64, 512, tid);
        __syncthreads();
        #pragma unroll
        for (int kk = 0; kk < 4; kk++) {
            int ks = c8 * 4 + kk;
            u32 aH[4], aL[4];
            u32 ab = sb + ((mt * 16 + lrow) * 72 + kk * 16 + lcol) * 2;
            ldmA(aH, ab); ldmA(aL, ab + ALo);
            const uint4* bf = g_woF + ((size_t)ks * 32 + nh * 16) * 32 + lane;
            #pragma unroll
            for (int g = 0; g < 16; g++) {
                uint4 f = bf[g * 32];
                u32 bh[2] = {f.x, f.y}, bl[2] = {f.z, f.w};
                mmabf(acc[g], aH, bh); mmabf(acc[g], aL, bh); mmabf(acc[g], aH, bl);
            }
        }
    }

    int ra = mt * 16 + (lane >> 2);
    float s_a = 0.f, q_a = 0.f, s_b = 0.f, q_b = 0.f;
    #pragma unroll
    for (int g = 0; g < 16; g++) {
        int c = nh * 128 + g * 8 + 2 * (lane & 3);
        float2 cb = *(const float2*)&bout[c];
        float v0 = acc[g][0] + cb.x, v1 = acc[g][1] + cb.y;
        float v2 = acc[g][2] + cb.x, v3 = acc[g][3] + cb.y;
        acc[g][0] = v0; acc[g][1] = v1; acc[g][2] = v2; acc[g][3] = v3;
        s_a += v0 + v1; q_a += v0 * v0 + v1 * v1;
        s_b += v2 + v3; q_b += v2 * v2 + v3 * v3;
    }
    s_a += __shfl_xor_sync(0xffffffffu, s_a, 1); s_a += __shfl_xor_sync(0xffffffffu, s_a, 2);
    q_a += __shfl_xor_sync(0xffffffffu, q_a, 1); q_a += __shfl_xor_sync(0xffffffffu, q_a, 2);
    s_b += __shfl_xor_sync(0xffffffffu, s_b, 1); s_b += __shfl_xor_sync(0xffffffffu, s_b, 2);
    q_b += __shfl_xor_sync(0xffffffffu, q_b, 1); q_b += __shfl_xor_sync(0xffffffffu, q_b, 2);
    if ((lane & 3) == 0) {
        ss[nh * 64 + ra] = s_a; sq[nh * 64 + ra] = q_a;
        ss[nh * 64 + ra + 8] = s_b; sq[nh * 64 + ra + 8] = q_b;
    }
    __syncthreads();
    float S0 = ss[ra] + ss[64 + ra], Q0 = sq[ra] + sq[64 + ra];
    float S1 = ss[ra + 8] + ss[64 + ra + 8], Q1 = sq[ra + 8] + sq[64 + ra + 8];
    float mu0 = S0 * (1.f / D), r0 = rsqrtf(Q0 * (1.f / D) - mu0 * mu0 + 1e-5f);
    float mu1 = S1 * (1.f / D), r1 = rsqrtf(Q1 * (1.f / D) - mu1 * mu1 + 1e-5f);
    #pragma unroll
    for (int g = 0; g < 16; g++) {
        int c = nh * 128 + g * 8 + 2 * (lane & 3);
        *(float2*)&out[(size_t)(t0 + ra) * D + c] =
            make_float2((acc[g][0] - mu0) * r0, (acc[g][1] - mu0) * r0);
        *(float2*)&out[(size_t)(t0 + ra + 8) * D + c] =
            make_float2((acc[g][2] - mu1) * r1, (acc[g][3] - mu1) * r1);
    }
}

// ---------------- launch ----------------
extern "C" void kernel_launch(void* const* d_in, const int* in_sizes, int n_in,
                              void* d_out, int out_size) {
    const float* x       = (const float*)d_in[0];
    const float* conv_w  = (const float*)d_in[1];
    const float* conv_b  = (const float*)d_in[2];
    const float* pattern = (const float*)d_in[3];
    const float* wq      = (const float*)d_in[4];
    const float* wkv     = (const float*)d_in[5];
    const float* wout    = (const float*)d_in[6];
    const float* bout    = (const float*)d_in[7];

    int T = in_sizes[0] / D;
    int B = in_sizes[8] - 1;
    int L = T / B;

    int convln_smem = 70720;
    int attn_smem   = 55808;
    int outln_smem  = 19456;
    cudaFuncSetAttribute(convln_kernel, cudaFuncAttributeMaxDynamicSharedMemorySize, convln_smem);
    cudaFuncSetAttribute(attn_kernel,   cudaFuncAttributeMaxDynamicSharedMemorySize, attn_smem);
    cudaFuncSetAttribute(outln_kernel,  cudaFuncAttributeMaxDynamicSharedMemorySize, outln_smem);

    prep_kernel <<<832, 256>>>(wq, wkv, wout, conv_w);         // 1
    kv_kernel   <<<PP, 256>>>(pattern);                        // 2
    convln_kernel<<<T / 64, 256, convln_smem>>>(x, conv_b, L); // 3
    dim3 ag(T / 64, HH);
    attn_kernel <<<ag, 256, attn_smem>>>();                    // 4 (profiled)
    outln_kernel<<<T / 64, 256, outln_smem>>>(bout, (float*)d_out); // 5
}

// round 17
// speedup vs baseline: 2.4674x; 1.0888x over previous
#include <cuda_runtime.h>
#include <cuda_bf16.h>

#define D    256
#define PP   512
#define HH   8
#define DA   64
#define TMAX 65536
typedef unsigned long long u64;
typedef unsigned int u32;
typedef unsigned short u16;

// ---------------- device scratch ----------------
__device__ __align__(16) __nv_bfloat16 g_ktH[HH * DA * PP];   // [h][d][p]
__device__ __align__(16) __nv_bfloat16 g_ktL[HH * DA * PP];
__device__ __align__(16) __nv_bfloat16 g_vH [HH * PP * DA];   // [h][p][d]
__device__ __align__(16) __nv_bfloat16 g_vL [HH * PP * DA];
__device__ __align__(16) __nv_bfloat16 g_xnH[(size_t)TMAX * D];
__device__ __align__(16) __nv_bfloat16 g_xnL[(size_t)TMAX * D];
__device__ __align__(16) __nv_bfloat16 g_attH[(size_t)TMAX * 512];
__device__ __align__(16) __nv_bfloat16 g_attL[(size_t)TMAX * 512];
__device__ __align__(16) __nv_bfloat16 g_wqTH[256 * 512];     // [k][j]
__device__ __align__(16) __nv_bfloat16 g_wqTL[256 * 512];
__device__ uint4 g_cwF[48 * 32 * 32];
__device__ uint4 g_woF[32 * 32 * 32];
__device__ float g_wkvT[D * 1024];

// ---------------- helpers ----------------
__device__ __forceinline__ void splitf(float v, u16& h, u16& l) {
    __nv_bfloat16 hb = __float2bfloat16(v);
    __nv_bfloat16 lb = __float2bfloat16(v - __bfloat162float(hb));
    h = __bfloat16_as_ushort(hb); l = __bfloat16_as_ushort(lb);
}
__device__ __forceinline__ u32 pckh(u16 a, u16 b) {
    u32 r; asm("mov.b32 %0,{%1,%2};" : "=r"(r) : "h"(a), "h"(b)); return r;
}
__device__ __forceinline__ u32 s2u(const void* p) {
    u32 a; asm("{ .reg .u64 t; cvta.to.shared.u64 t, %1; cvt.u32.u64 %0, t; }" : "=r"(a) : "l"(p));
    return a;
}
__device__ __forceinline__ void ldmA(u32* r, u32 a) {
    asm volatile("ldmatrix.sync.aligned.m8n8.x4.shared.b16 {%0,%1,%2,%3}, [%4];"
        : "=r"(r[0]), "=r"(r[1]), "=r"(r[2]), "=r"(r[3]) : "r"(a));
}
__device__ __forceinline__ void ldmB(u32* r, u32 a) {
    asm volatile("ldmatrix.sync.aligned.m8n8.x4.trans.shared.b16 {%0,%1,%2,%3}, [%4];"
        : "=r"(r[0]), "=r"(r[1]), "=r"(r[2]), "=r"(r[3]) : "r"(a));
}
__device__ __forceinline__ void mmabf(float* d, const u32* a, const u32* b) {
    asm volatile("mma.sync.aligned.m16n8k16.row.col.f32.bf16.bf16.f32 "
        "{%0,%1,%2,%3},{%4,%5,%6,%7},{%8,%9},{%0,%1,%2,%3};"
        : "+f"(d[0]), "+f"(d[1]), "+f"(d[2]), "+f"(d[3])
        : "r"(a[0]), "r"(a[1]), "r"(a[2]), "r"(a[3]), "r"(b[0]), "r"(b[1]));
}
__device__ __forceinline__ void stageB16(char* dst, const __nv_bfloat16* src, int rstride, int tid) {
    int r = tid >> 2, cb = (tid & 3) << 4;
    const uint4* s = (const uint4*)(src + (size_t)r * rstride + cb);
    uint4* d = (uint4*)(dst + (r * 72 + cb) * 2);
    d[0] = s[0]; d[1] = s[1];
}
__device__ __forceinline__ uint4 mkfrag(float b0a, float b0b, float b1a, float b1b) {
    u16 h0, l0, h1, l1; uint4 r;
    splitf(b0a, h0, l0); splitf(b0b, h1, l1); r.x = pckh(h0, h1); r.z = pckh(l0, l1);
    splitf(b1a, h0, l0); splitf(b1b, h1, l1); r.y = pckh(h0, h1); r.w = pckh(l0, l1);
    return r;
}
__device__ __forceinline__ float2 rec2(const char* smem, int lo_off, int off) {
    u32 hh = *(const u32*)(smem + off * 2);
    u32 ll = *(const u32*)(smem + lo_off + off * 2);
    float2 r;
    r.x = __bfloat162float(__ushort_as_bfloat16((u16)hh)) + __bfloat162float(__ushort_as_bfloat16((u16)ll));
    r.y = __bfloat162float(__ushort_as_bfloat16((u16)(hh >> 16))) + __bfloat162float(__ushort_as_bfloat16((u16)(ll >> 16)));
    return r;
}

// ---------------- launch 1: weight prep (grid 832 x 256) ----------------
__global__ void prep_kernel(const float* __restrict__ wq,
                            const float* __restrict__ wkv,
                            const float* __restrict__ wout,
                            const float* __restrict__ cw) {
    int bid = blockIdx.x, t = threadIdx.x;
    if (bid < 128) {
        int e = bid * 256 + t;
        int ks = e >> 10, n8 = (e >> 5) & 31, lane = e & 31;
        int k0 = ks * 16 + (lane & 3) * 2, c = n8 * 8 + (lane >> 2);
        const float* w = wout + (size_t)c * 512;
        g_woF[e] = mkfrag(w[k0], w[k0 + 1], w[k0 + 8], w[k0 + 9]);
    } else if (bid < 320) {
        int e = (bid - 128) * 256 + t;
        int ks = e >> 10, n8 = (e >> 5) & 31, lane = e & 31;
        int k0 = ks * 16 + (lane & 3) * 2, c = n8 * 8 + (lane >> 2);
        const float* w = cw + (size_t)c * 768;
        float b[4];
        #pragma unroll
        for (int q = 0; q < 4; q++) {
            int k = k0 + ((q & 1) ? 1 : 0) + ((q >> 1) ? 8 : 0);
            b[q] = w[(k & 255) * 3 + (k >> 8)];
        }
        g_cwF[e] = mkfrag(b[0], b[1], b[2], b[3]);
    } else if (bid < 576) {
        int k = bid - 320;
        #pragma unroll
        for (int u = 0; u < 4; u++)
            g_wkvT[k * 1024 + t + u * 256] = wkv[(size_t)(t + u * 256) * 256 + k];
    } else {
        int k = bid - 576;
        u16 h0, l0;
        splitf(wq[t * 256 + k], h0, l0);
        g_wqTH[k * 512 + t] = __ushort_as_bfloat16(h0);
        g_wqTL[k * 512 + t] = __ushort_as_bfloat16(l0);
        splitf(wq[(t + 256) * 256 + k], h0, l0);
        g_wqTH[k * 512 + t + 256] = __ushort_as_bfloat16(h0);
        g_wqTL[k * 512 + t + 256] = __ushort_as_bfloat16(l0);
    }
}

// ---------------- launch 2: pattern double-LN + kv projection ----------------
__device__ __forceinline__ float block_reduce_sum256(float v, float* scratch) {
    #pragma unroll
    for (int o = 16; o; o >>= 1) v += __shfl_xor_sync(0xffffffffu, v, o);
    int w = threadIdx.x >> 5;
    if ((threadIdx.x & 31) == 0) scratch[w] = v;
    __syncthreads();
    if (threadIdx.x < 32) {
        float s = (threadIdx.x < 8) ? scratch[threadIdx.x] : 0.f;
        #pragma unroll
        for (int o = 4; o; o >>= 1) s += __shfl_xor_sync(0xffffffffu, s, o);
        if (threadIdx.x == 0) scratch[0] = s;
    }
    __syncthreads();
    float r = scratch[0];
    __syncthreads();
    return r;
}

__global__ void kv_kernel(const float* __restrict__ pattern) {
    __shared__ float scr[8];
    __shared__ float pr[D];
    int p = blockIdx.x, t = threadIdx.x;
    float v = pattern[p * D + t];
    #pragma unroll
    for (int rep = 0; rep < 2; rep++) {
        float s  = block_reduce_sum256(v, scr);
        float s2 = block_reduce_sum256(v * v, scr);
        float mu = s * (1.f / D);
        v = (v - mu) * rsqrtf(s2 * (1.f / D) - mu * mu + 1e-5f);
    }
    pr[t] = v;
    __syncthreads();
    float acc[4] = {0.f, 0.f, 0.f, 0.f};
    for (int i = 0; i < D; i++) {
        float xv = pr[i];
        const float* wr = g_wkvT + i * 1024 + t;
        #pragma unroll
        for (int u = 0; u < 4; u++) acc[u] = fmaf(xv, wr[u * 256], acc[u]);
    }
    #pragma unroll
    for (int u = 0; u < 4; u++) {
        int j = t + u * 256;
        int h = j >> 7, r = j & 127;
        u16 hi, lo; splitf(acc[u], hi, lo);
        if (r < DA) {
            g_ktH[((size_t)(h * 64) + r) * 512 + p] = __ushort_as_bfloat16(hi);
            g_ktL[((size_t)(h * 64) + r) * 512 + p] = __ushort_as_bfloat16(lo);
        } else {
            g_vH[((size_t)(h * 512) + p) * 64 + (r - DA)] = __ushort_as_bfloat16(hi);
            g_vL[((size_t)(h * 512) + p) * 64 + (r - DA)] = __ushort_as_bfloat16(lo);
        }
    }
}

// ---------------- launch 3: HMMA conv + residual + leaky + LN ----------------
__global__ __launch_bounds__(256) void convln_kernel(const float* __restrict__ x,
                                                     const float* __restrict__ conv_b,
                                                     int L) {
    extern __shared__ char smem[];
    const int XLo = 34848;
    float* ss = (float*)(smem + 69696);
    float* sq = ss + 128;
    u32 sb = s2u(smem);
    int tid = threadIdx.x, lane = tid & 31, w = tid >> 5;
    int mt = w & 3, nh = w >> 2;
    int t0 = blockIdx.x * 64;
    int pos0 = t0 % L;
    int lrow = lane & 15, lcol = (lane >> 4) << 3;

    {
        int c2 = tid & 127, rg = tid >> 7;
        for (int r = rg; r < 66; r += 2) {
            float2 v = make_float2(0.f, 0.f);
            if (pos0 + r >= 2) v = *(const float2*)&x[(size_t)(t0 + r - 2) * D + 2 * c2];
            u16 h0, l0, h1, l1; splitf(v.x, h0, l0); splitf(v.y, h1, l1);
            *(u32*)(smem + (r * 264 + 2 * c2) * 2)       = pckh(h0, h1);
            *(u32*)(smem + XLo + (r * 264 + 2 * c2) * 2) = pckh(l0, l1);
        }
    }
    __syncthreads();

    float acc[16][4];
    #pragma unroll
    for (int g = 0; g < 16; g++)
        #pragma unroll
        for (int q = 0; q < 4; q++) acc[g][q] = 0.f;

    for (int tap = 0; tap < 3; tap++) {
        for (int kk = 0; kk < 16; kk++) {
            int ks = tap * 16 + kk;
            u32 aH[4], aL[4];
            u32 ab = sb + ((mt * 16 + lrow + tap) * 264 + kk * 16 + lcol) * 2;
            ldmA(aH, ab); ldmA(aL, ab + XLo);
            const uint4* bf = g_cwF + ((size_t)ks * 32 + nh * 16) * 32 + lane;
            #pragma unroll
            for (int g = 0; g < 16; g++) {
                uint4 f = bf[g * 32];
                u32 bh[2] = {f.x, f.y}, bl[2] = {f.z, f.w};
                mmabf(acc[g], aH, bh); mmabf(acc[g], aL, bh); mmabf(acc[g], aH, bl);
            }
        }
    }

    int ra = mt * 16 + (lane >> 2);
    float s_a = 0.f, q_a = 0.f, s_b = 0.f, q_b = 0.f;
    #pragma unroll
    for (int g = 0; g < 16; g++) {
        int c = nh * 128 + g * 8 + 2 * (lane & 3);
        float2 cb = *(const float2*)&conv_b[c];
        float2 xr0 = rec2(smem, XLo, (ra + 2) * 264 + c);
        float2 xr1 = rec2(smem, XLo, (ra + 10) * 264 + c);
        float v0 = acc[g][0] + cb.x + xr0.x, v1 = acc[g][1] + cb.y + xr0.y;
        float v2 = acc[g][2] + cb.x + xr1.x, v3 = acc[g][3] + cb.y + xr1.y;
        v0 = v0 > 0.f ? v0 : 0.01f * v0; v1 = v1 > 0.f ? v1 : 0.01f * v1;
        v2 = v2 > 0.f ? v2 : 0.01f * v2; v3 = v3 > 0.f ? v3 : 0.01f * v3;
        acc[g][0] = v0; acc[g][1] = v1; acc[g][2] = v2; acc[g][3] = v3;
        s_a += v0 + v1; q_a += v0 * v0 + v1 * v1;
        s_b += v2 + v3; q_b += v2 * v2 + v3 * v3;
    }
    s_a += __shfl_xor_sync(0xffffffffu, s_a, 1); s_a += __shfl_xor_sync(0xffffffffu, s_a, 2);
    q_a += __shfl_xor_sync(0xffffffffu, q_a, 1); q_a += __shfl_xor_sync(0xffffffffu, q_a, 2);
    s_b += __shfl_xor_sync(0xffffffffu, s_b, 1); s_b += __shfl_xor_sync(0xffffffffu, s_b, 2);
    q_b += __shfl_xor_sync(0xffffffffu, q_b, 1); q_b += __shfl_xor_sync(0xffffffffu, q_b, 2);
    if ((lane & 3) == 0) {
        ss[nh * 64 + ra] = s_a; sq[nh * 64 + ra] = q_a;
        ss[nh * 64 + ra + 8] = s_b; sq[nh * 64 + ra + 8] = q_b;
    }
    __syncthreads();
    float S0 = ss[ra] + ss[64 + ra], Q0 = sq[ra] + sq[64 + ra];
    float S1 = ss[ra + 8] + ss[64 + ra + 8], Q1 = sq[ra + 8] + sq[64 + ra + 8];
    float mu0 = S0 * (1.f / D), rs0 = rsqrtf(Q0 * (1.f / D) - mu0 * mu0 + 1e-5f);
    float mu1 = S1 * (1.f / D), rs1 = rsqrtf(Q1 * (1.f / D) - mu1 * mu1 + 1e-5f);
    #pragma unroll
    for (int g = 0; g < 16; g++) {
        int c = nh * 128 + g * 8 + 2 * (lane & 3);
        u16 h0, l0, h1, l1;
        splitf((acc[g][0] - mu0) * rs0, h0, l0); splitf((acc[g][1] - mu0) * rs0, h1, l1);
        *(u32*)&g_xnH[(size_t)(t0 + ra) * D + c] = pckh(h0, h1);
        *(u32*)&g_xnL[(size_t)(t0 + ra) * D + c] = pckh(l0, l1);
        splitf((acc[g][2] - mu1) * rs1, h0, l0); splitf((acc[g][3] - mu1) * rs1, h1, l1);
        *(u32*)&g_xnH[(size_t)(t0 + ra + 8) * D + c] = pckh(h0, h1);
        *(u32*)&g_xnL[(size_t)(t0 + ra + 8) * D + c] = pckh(l0, l1);
    }
}

// ---------------- launch 4 (PROFILED): HMMA attn, 128-token tile + double buffer ----------------
// grid (T/128, 8), 256 thr. smem: QH@0(18432) QL@18432 stage@36864: 2 x {KH,KL,VH,VL} x 9216
// total 110592 B
__global__ __launch_bounds__(256, 2) void attn_kernel() {
    extern __shared__ char smem[];
    const int QLo = 18432, ST = 36864, SLOT = 9216, HALF = 36864;
    u32 sb = s2u(smem);
    int tid = threadIdx.x, lane = tid & 31, w = tid >> 5;
    int mt = w & 3, nh = w >> 2;
    int t0 = blockIdx.x * 128, h = blockIdx.y;
    int lrow = lane & 15, lcol = (lane >> 4) << 3;

    // ---- qproj, two 64-token halves (R16 structure) ----
    for (int ht = 0; ht < 2; ht++) {
        float qD[4][4];
        #pragma unroll
        for (int i = 0; i < 4; i++)
            #pragma unroll
            for (int j = 0; j < 4; j++) qD[i][j] = 0.f;
        for (int c = 0; c < 4; c++) {
            __syncthreads();
            stageB16(smem + ST,            g_xnH + (size_t)(t0 + ht * 64) * D + c * 64, D, tid);
            stageB16(smem + ST + SLOT,     g_xnL + (size_t)(t0 + ht * 64) * D + c * 64, D, tid);
            stageB16(smem + ST + 2 * SLOT, g_wqTH + (size_t)(c * 64) * 512 + h * 64, 512, tid);
            stageB16(smem + ST + 3 * SLOT, g_wqTL + (size_t)(c * 64) * 512 + h * 64, 512, tid);
            __syncthreads();
            #pragma unroll
            for (int ks = 0; ks < 4; ks++) {
                int kb = ks * 16;
                u32 aH[4], aL[4];
                ldmA(aH, sb + ST + ((mt * 16 + lrow) * 72 + kb + lcol) * 2);
                ldmA(aL, sb + ST + SLOT + ((mt * 16 + lrow) * 72 + kb + lcol) * 2);
                #pragma unroll
                for (int ng = 0; ng < 2; ng++) {
                    int nb = nh * 32 + ng * 16;
                    u32 bH[4], bL[4];
                    ldmB(bH, sb + ST + 2 * SLOT + ((kb + lrow) * 72 + nb + lcol) * 2);
                    ldmB(bL, sb + ST + 3 * SLOT + ((kb + lrow) * 72 + nb + lcol) * 2);
                    #pragma unroll
                    for (int ti = 0; ti < 2; ti++) {
                        u32 bh2[2] = {bH[2 * ti], bH[2 * ti + 1]};
                        u32 bl2[2] = {bL[2 * ti], bL[2 * ti + 1]};
                        float* dd = qD[ng * 2 + ti];
                        mmabf(dd, aH, bh2); mmabf(dd, aL, bh2); mmabf(dd, aH, bl2);
                    }
                }
            }
        }
        int r0 = ht * 64 + mt * 16 + (lane >> 2);
        #pragma unroll
        for (int nt = 0; nt < 4; nt++) {
            int c0 = nh * 32 + nt * 8 + 2 * (lane & 3);
            u16 h0, l0, h1, l1;
            splitf(qD[nt][0], h0, l0); splitf(qD[nt][1], h1, l1);
            *(u32*)(smem + (r0 * 72 + c0) * 2) = pckh(h0, h1);
            *(u32*)(smem + QLo + (r0 * 72 + c0) * 2) = pckh(l0, l1);
            splitf(qD[nt][2], h0, l0); splitf(qD[nt][3], h1, l1);
            *(u32*)(smem + ((r0 + 8) * 72 + c0) * 2) = pckh(h0, h1);
            *(u32*)(smem + QLo + ((r0 + 8) * 72 + c0) * 2) = pckh(l0, l1);
        }
    }
    __syncthreads();

    // ---- Q fragments to registers (warp w -> rows w*16..+15, full k=64) ----
    u32 qaH[4][4], qaL[4][4];
    #pragma unroll
    for (int ks = 0; ks < 4; ks++) {
        ldmA(qaH[ks], sb + ((w * 16 + lrow) * 72 + ks * 16 + lcol) * 2);
        ldmA(qaL[ks], sb + QLo + ((w * 16 + lrow) * 72 + ks * 16 + lcol) * 2);
    }
    // prefetch batch 0 into buffer 0
    stageB16(smem + ST,            g_ktH + (size_t)(h * 64) * 512, 512, tid);
    stageB16(smem + ST + SLOT,     g_ktL + (size_t)(h * 64) * 512, 512, tid);
    stageB16(smem + ST + 2 * SLOT, g_vH + (size_t)(h * 512) * 64, 64, tid);
    stageB16(smem + ST + 3 * SLOT, g_vL + (size_t)(h * 512) * 64, 64, tid);
    __syncthreads();

    float pvD[8][4];
    #pragma unroll
    for (int i = 0; i < 8; i++)
        #pragma unroll
        for (int j = 0; j < 4; j++) pvD[i][j] = 0.f;
    float rsum0 = 0.f, rsum1 = 0.f;

    for (int b = 0; b < 8; b++) {
        int cb0 = ST + (b & 1) * HALF;
        if (b + 1 < 8) {
            int nb0 = ST + ((b + 1) & 1) * HALF;
            stageB16(smem + nb0,            g_ktH + (size_t)(h * 64) * 512 + (b + 1) * 64, 512, tid);
            stageB16(smem + nb0 + SLOT,     g_ktL + (size_t)(h * 64) * 512 + (b + 1) * 64, 512, tid);
            stageB16(smem + nb0 + 2 * SLOT, g_vH + ((size_t)(h * 512) + (b + 1) * 64) * 64, 64, tid);
            stageB16(smem + nb0 + 3 * SLOT, g_vL + ((size_t)(h * 512) + (b + 1) * 64) * 64, 64, tid);
        }
        // scores: full 64-pat width per warp
        float sD[8][4];
        #pragma unroll
        for (int i = 0; i < 8; i++)
            #pragma unroll
            for (int j = 0; j < 4; j++) sD[i][j] = 0.f;
        #pragma unroll
        for (int ks = 0; ks < 4; ks++) {
            #pragma unroll
            for (int ng = 0; ng < 4; ng++) {
                u32 bH[4], bL[4];
                ldmB(bH, sb + cb0 + ((ks * 16 + lrow) * 72 + ng * 16 + lcol) * 2);
                ldmB(bL, sb + cb0 + SLOT + ((ks * 16 + lrow) * 72 + ng * 16 + lcol) * 2);
                #pragma unroll
                for (int ti = 0; ti < 2; ti++) {
                    u32 bh2[2] = {bH[2 * ti], bH[2 * ti + 1]};
                    u32 bl2[2] = {bL[2 * ti], bL[2 * ti + 1]};
                    float* dd = sD[ng * 2 + ti];
                    mmabf(dd, qaH[ks], bh2); mmabf(dd, qaL[ks], bh2); mmabf(dd, qaH[ks], bl2);
                }
            }
        }
        // exp + pack probs as PV A-fragments (kp = 16-pattern step)
        u32 paH[4][4], paL[4][4];
        #pragma unroll
        for (int kp = 0; kp < 4; kp++) {
            float e0 = __expf(0.125f * sD[2 * kp][0]),     e1 = __expf(0.125f * sD[2 * kp][1]);
            float e2 = __expf(0.125f * sD[2 * kp][2]),     e3 = __expf(0.125f * sD[2 * kp][3]);
            float e4 = __expf(0.125f * sD[2 * kp + 1][0]), e5 = __expf(0.125f * sD[2 * kp + 1][1]);
            float e6 = __expf(0.125f * sD[2 * kp + 1][2]), e7 = __expf(0.125f * sD[2 * kp + 1][3]);
            rsum0 += e0 + e1 + e4 + e5;
            rsum1 += e2 + e3 + e6 + e7;
            u16 h0, l0, h1, l1;
            splitf(e0, h0, l0); splitf(e1, h1, l1); paH[kp][0] = pckh(h0, h1); paL[kp][0] = pckh(l0, l1);
            splitf(e2, h0, l0); splitf(e3, h1, l1); paH[kp][1] = pckh(h0, h1); paL[kp][1] = pckh(l0, l1);
            splitf(e4, h0, l0); splitf(e5, h1, l1); paH[kp][2] = pckh(h0, h1); paL[kp][2] = pckh(l0, l1);
            splitf(e6, h0, l0); splitf(e7, h1, l1); paH[kp][3] = pckh(h0, h1); paL[kp][3] = pckh(l0, l1);
        }
        // PV: full 64-d width per warp
        #pragma unroll
        for (int kp = 0; kp < 4; kp++) {
            #pragma unroll
            for (int ng = 0; ng < 4; ng++) {
                u32 vH[4], vL[4];
                ldmB(vH, sb + cb0 + 2 * SLOT + ((kp * 16 + lrow) * 72 + ng * 16 + lcol) * 2);
                ldmB(vL, sb + cb0 + 3 * SLOT + ((kp * 16 + lrow) * 72 + ng * 16 + lcol) * 2);
                #pragma unroll
                for (int ti = 0; ti < 2; ti++) {
                    u32 vh2[2] = {vH[2 * ti], vH[2 * ti + 1]};
                    u32 vl2[2] = {vL[2 * ti], vL[2 * ti + 1]};
                    float* dd = pvD[ng * 2 + ti];
                    mmabf(dd, paH[kp], vh2); mmabf(dd, paL[kp], vh2); mmabf(dd, paH[kp], vl2);
                }
            }
        }
        __syncthreads();
    }
    // ---- normalize + split-store (warp-complete rows, no cross-warp reduce) ----
    rsum0 += __shfl_xor_sync(0xffffffffu, rsum0, 1);
    rsum0 += __shfl_xor_sync(0xffffffffu, rsum0, 2);
    rsum1 += __shfl_xor_sync(0xffffffffu, rsum1, 1);
    rsum1 += __shfl_xor_sync(0xffffffffu, rsum1, 2);
    float ri0 = 1.f / rsum0, ri1 = 1.f / rsum1;
    int r0 = w * 16 + (lane >> 2);
    #pragma unroll
    for (int nt = 0; nt < 8; nt++) {
        int c = nt * 8 + 2 * (lane & 3);
        u16 h0, l0, h1, l1;
        splitf(pvD[nt][0] * ri0, h0, l0); splitf(pvD[nt][1] * ri0, h1, l1);
        *(u32*)&g_attH[(size_t)(t0 + r0) * 512 + h * 64 + c] = pckh(h0, h1);
        *(u32*)&g_attL[(size_t)(t0 + r0) * 512 + h * 64 + c] = pckh(l0, l1);
        splitf(pvD[nt][2] * ri1, h0, l0); splitf(pvD[nt][3] * ri1, h1, l1);
        *(u32*)&g_attH[(size_t)(t0 + r0 + 8) * 512 + h * 64 + c] = pckh(h0, h1);
        *(u32*)&g_attL[(size_t)(t0 + r0 + 8) * 512 + h * 64 + c] = pckh(l0, l1);
    }
}

// ---------------- launch 5: HMMA out projection + final LN ----------------
__global__ __launch_bounds__(256) void outln_kernel(const float* __restrict__ bout,
                                                    float* __restrict__ out) {
    extern __shared__ char smem[];
    const int ALo = 9216;
    float* ss = (float*)(smem + 18432);
    float* sq = ss + 128;
    u32 sb = s2u(smem);
    int tid = threadIdx.x, lane = tid & 31, w = tid >> 5;
    int mt = w & 3, nh = w >> 2;
    int t0 = blockIdx.x * 64;
    int lrow = lane & 15, lcol = (lane >> 4) << 3;

    float acc[16][4];
    #pragma unroll
    for (int g = 0; g < 16; g++)
        #pragma unroll
        for (int q = 0; q < 4; q++) acc[g][q] = 0.f;

    for (int c8 = 0; c8 < 8; c8++) {
        __syncthreads();
        stageB16(smem, g_attH + (size_t)t0 * 512 + c8 * 64, 512, tid);
        stageB16(smem + ALo, g_attL + (size_t)t0 * 512 + c8 * 64, 512, tid);
        __syncthreads();
        #pragma unroll
        for (int kk = 0; kk < 4; kk++) {
            int ks = c8 * 4 + kk;
            u32 aH[4], aL[4];
            u32 ab = sb + ((mt * 16 + lrow) * 72 + kk * 16 + lcol) * 2;
            ldmA(aH, ab); ldmA(aL, ab + ALo);
            const uint4* bf = g_woF + ((size_t)ks * 32 + nh * 16) * 32 + lane;
            #pragma unroll
            for (int g = 0; g < 16; g++) {
                uint4 f = bf[g * 32];
                u32 bh[2] = {f.x, f.y}, bl[2] = {f.z, f.w};
                mmabf(acc[g], aH, bh); mmabf(acc[g], aL, bh); mmabf(acc[g], aH, bl);
            }
        }
    }

    int ra = mt * 16 + (lane >> 2);
    float s_a = 0.f, q_a = 0.f, s_b = 0.f, q_b = 0.f;
    #pragma unroll
    for (int g = 0; g < 16; g++) {
        int c = nh * 128 + g * 8 + 2 * (lane & 3);
        float2 cb = *(const float2*)&bout[c];
        float v0 = acc[g][0] + cb.x, v1 = acc[g][1] + cb.y;
        float v2 = acc[g][2] + cb.x, v3 = acc[g][3] + cb.y;
        acc[g][0] = v0; acc[g][1] = v1; acc[g][2] = v2; acc[g][3] = v3;
        s_a += v0 + v1; q_a += v0 * v0 + v1 * v1;
        s_b += v2 + v3; q_b += v2 * v2 + v3 * v3;
    }
    s_a += __shfl_xor_sync(0xffffffffu, s_a, 1); s_a += __shfl_xor_sync(0xffffffffu, s_a, 2);
    q_a += __shfl_xor_sync(0xffffffffu, q_a, 1); q_a += __shfl_xor_sync(0xffffffffu, q_a, 2);
    s_b += __shfl_xor_sync(0xffffffffu, s_b, 1); s_b += __shfl_xor_sync(0xffffffffu, s_b, 2);
    q_b += __shfl_xor_sync(0xffffffffu, q_b, 1); q_b += __shfl_xor_sync(0xffffffffu, q_b, 2);
    if ((lane & 3) == 0) {
        ss[nh * 64 + ra] = s_a; sq[nh * 64 + ra] = q_a;
        ss[nh * 64 + ra + 8] = s_b; sq[nh * 64 + ra + 8] = q_b;
    }
    __syncthreads();
    float S0 = ss[ra] + ss[64 + ra], Q0 = sq[ra] + sq[64 + ra];
    float S1 = ss[ra + 8] + ss[64 + ra + 8], Q1 = sq[ra + 8] + sq[64 + ra + 8];
    float mu0 = S0 * (1.f / D), r0 = rsqrtf(Q0 * (1.f / D) - mu0 * mu0 + 1e-5f);
    float mu1 = S1 * (1.f / D), r1 = rsqrtf(Q1 * (1.f / D) - mu1 * mu1 + 1e-5f);
    #pragma unroll
    for (int g = 0; g < 16; g++) {
        int c = nh * 128 + g * 8 + 2 * (lane & 3);
        *(float2*)&out[(size_t)(t0 + ra) * D + c] =
            make_float2((acc[g][0] - mu0) * r0, (acc[g][1] - mu0) * r0);
        *(float2*)&out[(size_t)(t0 + ra + 8) * D + c] =
            make_float2((acc[g][2] - mu1) * r1, (acc[g][3] - mu1) * r1);
    }
}

// ---------------- launch ----------------
extern "C" void kernel_launch(void* const* d_in, const int* in_sizes, int n_in,
                              void* d_out, int out_size) {
    const float* x       = (const float*)d_in[0];
    const float* conv_w  = (const float*)d_in[1];
    const float* conv_b  = (const float*)d_in[2];
    const float* pattern = (const float*)d_in[3];
    const float* wq      = (const float*)d_in[4];
    const float* wkv     = (const float*)d_in[5];
    const float* wout    = (const float*)d_in[6];
    const float* bout    = (const float*)d_in[7];

    int T = in_sizes[0] / D;
    int B = in_sizes[8] - 1;
    int L = T / B;

    int convln_smem = 70720;
    int attn_smem   = 110592;
    int outln_smem  = 19456;
    cudaFuncSetAttribute(convln_kernel, cudaFuncAttributeMaxDynamicSharedMemorySize, convln_smem);
    cudaFuncSetAttribute(attn_kernel,   cudaFuncAttributeMaxDynamicSharedMemorySize, attn_smem);
    cudaFuncSetAttribute(outln_kernel,  cudaFuncAttributeMaxDynamicSharedMemorySize, outln_smem);

    prep_kernel <<<832, 256>>>(wq, wkv, wout, conv_w);         // 1
    kv_kernel   <<<PP, 256>>>(pattern);                        // 2
    convln_kernel<<<T / 64, 256, convln_smem>>>(x, conv_b, L); // 3
    dim3 ag(T / 128, HH);
    attn_kernel <<<ag, 256, attn_smem>>>();                    // 4 (profiled)
    outln_kernel<<<T / 64, 256, outln_smem>>>(bout, (float*)d_out); // 5
}